// round 12
// baseline (speedup 1.0000x reference)
#include <cuda_runtime.h>
#include <cuda_fp16.h>
#include <cstdint>
#include <cstddef>

// ---------------------------------------------------------------------------
// Problem constants
// ---------------------------------------------------------------------------
#define BB   2
#define SS   2048
#define DD   1024
#define HH   16
#define DHH  64
#define DMM  4096
#define BSS  (BB * SS)          // 4096 rows
#define QKVN (3 * DD)           // 3072
#define LN_EPS 1e-5f
#define LOG2E 1.4426950408889634f

// ---------------------------------------------------------------------------
// Scratch (static device globals; fp16 single-precision path, fp32 accum)
// ---------------------------------------------------------------------------
__device__ __half g_x1[BSS * DD];                 // LN1 out
__device__ __half g_wqkv[QKVN * DD];              // [N=3072,K=1024]
__device__ float  g_bqkv[QKVN];
__device__ __half g_qkv[(size_t)BSS * QKVN];      // q(0.125*log2e-folded)|k|v
__device__ __half g_z[BSS * DD];                  // attention out
__device__ __half g_wo[DD * DD];                  // [N=1024,K=1024]
__device__ float  g_rmid[BSS * DD];
__device__ __half g_x2[BSS * DD];                 // LN2 out
__device__ __half g_win[DMM * DD];                // [N=4096,K=1024]
__device__ __half g_h[(size_t)BSS * DMM];         // MLP hidden
__device__ __half g_wout[DD * DMM];               // [N=1024,K=4096]

// ---------------------------------------------------------------------------
// PTX helpers (baseline ISA: ldmatrix / mma.sync / cp.async)
// ---------------------------------------------------------------------------
__device__ __forceinline__ uint32_t smem_u32(const void* p) {
    uint32_t a;
    asm("{ .reg .u64 t; cvta.to.shared.u64 t, %1; cvt.u32.u64 %0, t; }" : "=r"(a) : "l"(p));
    return a;
}
__device__ __forceinline__ void ldsm4(uint32_t& r0, uint32_t& r1, uint32_t& r2,
                                      uint32_t& r3, uint32_t a) {
    asm volatile("ldmatrix.sync.aligned.m8n8.x4.shared.b16 {%0,%1,%2,%3}, [%4];"
                 : "=r"(r0), "=r"(r1), "=r"(r2), "=r"(r3) : "r"(a));
}
__device__ __forceinline__ void ldsm4t(uint32_t& r0, uint32_t& r1, uint32_t& r2,
                                       uint32_t& r3, uint32_t a) {
    asm volatile("ldmatrix.sync.aligned.m8n8.x4.trans.shared.b16 {%0,%1,%2,%3}, [%4];"
                 : "=r"(r0), "=r"(r1), "=r"(r2), "=r"(r3) : "r"(a));
}
__device__ __forceinline__ void mma16816(float* c, const uint32_t* a, const uint32_t* b) {
    asm volatile(
        "mma.sync.aligned.m16n8k16.row.col.f32.f16.f16.f32 "
        "{%0,%1,%2,%3},{%4,%5,%6,%7},{%8,%9},{%0,%1,%2,%3};"
        : "+f"(c[0]), "+f"(c[1]), "+f"(c[2]), "+f"(c[3])
        : "r"(a[0]), "r"(a[1]), "r"(a[2]), "r"(a[3]), "r"(b[0]), "r"(b[1]));
}
__device__ __forceinline__ void mma2(float* c, const uint32_t* a, uint32_t b0, uint32_t b1) {
    asm volatile(
        "mma.sync.aligned.m16n8k16.row.col.f32.f16.f16.f32 "
        "{%0,%1,%2,%3},{%4,%5,%6,%7},{%8,%9},{%0,%1,%2,%3};"
        : "+f"(c[0]), "+f"(c[1]), "+f"(c[2]), "+f"(c[3])
        : "r"(a[0]), "r"(a[1]), "r"(a[2]), "r"(a[3]), "r"(b0), "r"(b1));
}
__device__ __forceinline__ void cp16(uint32_t d, const void* s) {
    asm volatile("cp.async.cg.shared.global [%0], [%1], 16;" :: "r"(d), "l"(s) : "memory");
}
#define CP_COMMIT() asm volatile("cp.async.commit_group;" ::: "memory")

__device__ __forceinline__ uint32_t f2h2(float a, float b) {
    __half2 h = __floats2half2_rn(a, b);
    return *(uint32_t*)&h;
}

// ---------------------------------------------------------------------------
// Block reduction
// ---------------------------------------------------------------------------
__device__ __forceinline__ float block_sum(float v, float* red) {
    __syncthreads();
    int lane = threadIdx.x & 31, wid = threadIdx.x >> 5;
    #pragma unroll
    for (int o = 16; o > 0; o >>= 1) v += __shfl_xor_sync(0xffffffffu, v, o);
    if (lane == 0) red[wid] = v;
    __syncthreads();
    float t = (threadIdx.x < (blockDim.x >> 5)) ? red[threadIdx.x] : 0.f;
    if (wid == 0) {
        #pragma unroll
        for (int o = 16; o > 0; o >>= 1) t += __shfl_xor_sync(0xffffffffu, t, o);
        if (lane == 0) red[0] = t;
    }
    __syncthreads();
    return red[0];
}

// ---------------------------------------------------------------------------
// LN row body (register-resident, 256 threads x float4)
// ---------------------------------------------------------------------------
__device__ __forceinline__ void ln_body(const float* __restrict__ x,
                                        const float* __restrict__ w,
                                        const float* __restrict__ b,
                                        __half* __restrict__ o, int r, float* red) {
    int tid = threadIdx.x;
    float4 v = ((const float4*)(x + (size_t)r * DD))[tid];
    float s = block_sum(v.x + v.y + v.z + v.w, red);
    float mean = s * (1.f / DD);
    float dx = v.x - mean, dy = v.y - mean, dz = v.z - mean, dw = v.w - mean;
    float q = block_sum(dx * dx + dy * dy + dz * dz + dw * dw, red);
    float inv = rsqrtf(q * (1.f / DD) + LN_EPS);
    float4 w4 = ((const float4*)w)[tid];
    float4 b4 = ((const float4*)b)[tid];
    __half2 h0 = __floats2half2_rn(dx * inv * w4.x + b4.x, dy * inv * w4.y + b4.y);
    __half2 h1 = __floats2half2_rn(dz * inv * w4.z + b4.z, dw * inv * w4.w + b4.w);
    uint2 pk; pk.x = *(uint32_t*)&h0; pk.y = *(uint32_t*)&h1;
    ((uint2*)(o + (size_t)r * DD))[tid] = pk;
}

// conv_wT body: W fp32 [K,N] tile -> B fp16 [N,K]
__device__ __forceinline__ void wT_body(const float* __restrict__ W,
                                        __half* __restrict__ B, int K, int N,
                                        int n0, int k0, float* t /*32x33*/) {
    int tid = threadIdx.x;
    int tx = tid & 31, ty = tid >> 5;   // ty 0..7
    #pragma unroll
    for (int i = 0; i < 4; i++)
        t[(ty + i * 8) * 33 + tx] = W[(size_t)(k0 + ty + i * 8) * N + n0 + tx];
    __syncthreads();
    #pragma unroll
    for (int i = 0; i < 4; i++) {
        int n = n0 + ty + i * 8, k = k0 + tx;
        B[(size_t)n * K + k] = __float2half_rn(t[tx * 33 + ty + i * 8]);
    }
}

// ---------------------------------------------------------------------------
// prep_kernel: ALL weight conversions + bias pack + LN1 in ONE launch.
// ---------------------------------------------------------------------------
#define PREP_BLOCKS 13828

__global__ __launch_bounds__(256)
void prep_kernel(const float* __restrict__ WQ, const float* __restrict__ WK,
                 const float* __restrict__ WV, const float* __restrict__ bQ,
                 const float* __restrict__ bK, const float* __restrict__ bV,
                 const float* __restrict__ WO, const float* __restrict__ Win,
                 const float* __restrict__ Wout, const float* __restrict__ resid,
                 const float* __restrict__ ln1w, const float* __restrict__ ln1b) {
    __shared__ float smf[32 * 65];
    int bid = blockIdx.x;
    int tid = threadIdx.x;

    if (bid < 4096) {
        int n0 = (bid & 127) * 32, k0 = (bid >> 7) * 32;
        wT_body(Win, g_win, DD, DMM, n0, k0, smf);
        return;
    }
    bid -= 4096;
    if (bid < 4096) {
        int n0 = (bid & 31) * 32, k0 = (bid >> 5) * 32;
        wT_body(Wout, g_wout, DMM, DD, n0, k0, smf);
        return;
    }
    bid -= 4096;
    if (bid < 4096) {
        ln_body(resid, ln1w, ln1b, g_x1, bid, smf);
        return;
    }
    bid -= 4096;
    if (bid < 1024) {
        int n0 = (bid & 31) * 32, k0 = (bid >> 5) * 32;
        wT_body(WO, g_wo, DD, DD, n0, k0, smf);
        return;
    }
    bid -= 1024;
    if (bid < 512) {
        int k0 = (bid & 31) * 32, h = bid >> 5;
        const float* Ws[3] = {WQ, WK, WV};
        for (int s = 0; s < 3; s++) {
            const float* src = Ws[s] + (size_t)h * DD * DHH + (size_t)k0 * DHH;
            #pragma unroll
            for (int it = 0; it < 8; it++) {
                int idx = tid + it * 256;
                smf[(idx >> 6) * 65 + (idx & 63)] = src[idx];
            }
            __syncthreads();
            #pragma unroll
            for (int it = 0; it < 8; it++) {
                int idx = tid + it * 256;
                int dh = idx >> 5, kk = idx & 31;
                size_t n = (size_t)s * DD + h * 64 + dh;
                g_wqkv[n * DD + k0 + kk] = __float2half_rn(smf[kk * 65 + dh]);
            }
            __syncthreads();
        }
        return;
    }
    bid -= 512;
    {
        int i = bid * 256 + tid;
        g_bqkv[i]          = bQ[i];
        g_bqkv[DD + i]     = bK[i];
        g_bqkv[2 * DD + i] = bV[i];
    }
}

__device__ __forceinline__ float gelu_tanh(float x) {
    float x3 = x * x * x;
    return 0.5f * x * (1.f + tanhf(0.7978845608028654f * (x + 0.044715f * x3)));
}

// ---------------------------------------------------------------------------
// LN2 (standalone; depends on rmid)
// ---------------------------------------------------------------------------
__global__ __launch_bounds__(256)
void ln_kernel(const float* __restrict__ x, const float* __restrict__ w,
               const float* __restrict__ b, __half* __restrict__ o) {
    __shared__ float red[32];
    ln_body(x, w, b, o, blockIdx.x, red);
}

// ---------------------------------------------------------------------------
// HMMA fp16 GEMM: C = A @ B^T + bias ; fp32 accumulate.
// 128x64 CTA tile, 256 threads, 8 warps (4x2), warp tile 32x32, K-tile 64.
// Smaller acc (32 regs) -> 3 CTAs/SM for latency hiding (occ was 19.6%).
// 144B smem pitch (conflict-free). Double-buffered cp.async.
// EPI: 1 bias+gelu -> fp16 ; 2 bias+residual -> fp32 ; 3 bias (Q cols *0.125*log2e) -> fp16
// ---------------------------------------------------------------------------
#define GA_BYTES 18432               // A: 128 rows * 144 B
#define GB_BYTES 9216                // B:  64 rows * 144 B
#define GBUF (GA_BYTES + GB_BYTES)   // 27648 per stage
#define GEMM_SMEM (2 * GBUF)         // 55296

__device__ __forceinline__ void gemm_load(uint32_t dst, const char* srcA,
                                          const char* srcB, size_t rowB,
                                          int k0b, int tid) {
    // A: 128 rows x 8 chunks = 1024 ; B: 64 x 8 = 512 ; total 1536 = 256*6
    #pragma unroll
    for (int it = 0; it < 6; it++) {
        int idx = tid + it * 256;
        if (idx < 1024) {
            int row = idx >> 3, kc = idx & 7;
            cp16(dst + row * 144 + kc * 16, srcA + (size_t)row * rowB + k0b + kc * 16);
        } else {
            int r = idx - 1024;
            int row = r >> 3, kc = r & 7;
            cp16(dst + GA_BYTES + row * 144 + kc * 16,
                 srcB + (size_t)row * rowB + k0b + kc * 16);
        }
    }
    CP_COMMIT();
}

template <int EPI>
__global__ __launch_bounds__(256, 3)
void gemm_hmma(const __half* __restrict__ A, const __half* __restrict__ B,
               const float* __restrict__ bias, const float* __restrict__ R,
               float* __restrict__ Cf, __half* __restrict__ Ch,
               int M, int N, int K) {
    extern __shared__ char sm[];
    const uint32_t sb = smem_u32(sm);
    const int tid = threadIdx.x;
    const int wid = tid >> 5, lid = tid & 31;
    const int warp_m = wid >> 1, warp_n = wid & 1;   // 4x2 warp grid, 32x32 tiles

    const char* srcA = (const char*)(A + (size_t)blockIdx.y * 128 * K);
    const char* srcB = (const char*)(B + (size_t)blockIdx.x * 64 * K);
    const size_t rowB = (size_t)K * 2;

    const int g = lid >> 3, li = lid & 7;
    const int a_row = (g & 1) * 8 + li, a_kb = (g >> 1) * 16;
    const int b_row = (g >> 1) * 8 + li, b_kb = (g & 1) * 16;

    float acc[2][4][4];
    #pragma unroll
    for (int mt = 0; mt < 2; mt++)
        #pragma unroll
        for (int nt = 0; nt < 4; nt++)
            #pragma unroll
            for (int e = 0; e < 4; e++) acc[mt][nt][e] = 0.f;

    const int T = K >> 6;   // K-tiles of 64

    gemm_load(sb, srcA, srcB, rowB, 0, tid);
    gemm_load(sb + GBUF, srcA, srcB, rowB, 128, tid);

    for (int t = 0; t < T; t++) {
        if (t + 1 < T) { asm volatile("cp.async.wait_group 1;" ::: "memory"); }
        else           { asm volatile("cp.async.wait_group 0;" ::: "memory"); }
        __syncthreads();

        uint32_t buf = sb + (t & 1) * GBUF;
        uint32_t aP = buf + (warp_m * 32 + a_row) * 144 + a_kb;
        uint32_t bP = buf + GA_BYTES + (warp_n * 32 + b_row) * 144 + b_kb;

        #pragma unroll
        for (int kk = 0; kk < 4; kk++) {
            uint32_t bh[4][2];
            ldsm4(bh[0][0], bh[0][1], bh[1][0], bh[1][1], bP + kk * 32);
            ldsm4(bh[2][0], bh[2][1], bh[3][0], bh[3][1], bP + 16 * 144 + kk * 32);
            #pragma unroll
            for (int mt = 0; mt < 2; mt++) {
                uint32_t ah[4];
                ldsm4(ah[0], ah[1], ah[2], ah[3], aP + mt * 16 * 144 + kk * 32);
                #pragma unroll
                for (int nt = 0; nt < 4; nt++)
                    mma16816(acc[mt][nt], ah, bh[nt]);
            }
        }
        __syncthreads();

        if (t + 2 < T)
            gemm_load(sb + (t & 1) * GBUF, srcA, srcB, rowB, (t + 2) * 128, tid);
    }

    const int group = lid >> 2, t4 = lid & 3;
    const size_t rbase = (size_t)blockIdx.y * 128 + warp_m * 32;
    const int cbase = blockIdx.x * 64 + warp_n * 32;
    #pragma unroll
    for (int mt = 0; mt < 2; mt++) {
        size_t r0 = rbase + mt * 16 + group;
        size_t r1 = r0 + 8;
        #pragma unroll
        for (int nt = 0; nt < 4; nt++) {
            int col = cbase + nt * 8 + t4 * 2;
            float* c = acc[mt][nt];
            float b0 = bias[col], b1 = bias[col + 1];
            float x0 = c[0] + b0, x1 = c[1] + b1;
            float x2 = c[2] + b0, x3 = c[3] + b1;
            if (EPI == 1 || EPI == 3) {
                if (EPI == 1) {
                    x0 = gelu_tanh(x0); x1 = gelu_tanh(x1);
                    x2 = gelu_tanh(x2); x3 = gelu_tanh(x3);
                } else {
                    // fold 1/sqrt(DH) AND log2(e) into Q -> scores are base-2 logits
                    float qsc = (blockIdx.x < 16) ? 0.125f * LOG2E : 1.0f;
                    x0 *= qsc; x1 *= qsc; x2 *= qsc; x3 *= qsc;
                }
                *(__half2*)(Ch + r0 * N + col) = __floats2half2_rn(x0, x1);
                *(__half2*)(Ch + r1 * N + col) = __floats2half2_rn(x2, x3);
            } else {
                float2 ra = *(const float2*)(R + r0 * N + col);
                float2 rb = *(const float2*)(R + r1 * N + col);
                x0 += ra.x; x1 += ra.y; x2 += rb.x; x3 += rb.y;
                float2 va; va.x = x0; va.y = x1;
                float2 vb; vb.x = x2; vb.y = x3;
                *(float2*)(Cf + r0 * N + col) = va;
                *(float2*)(Cf + r1 * N + col) = vb;
            }
        }
    }
}

// ---------------------------------------------------------------------------
// flash2: tensor-core causal flash attention. Base-2 softmax (log2e folded
// into Q), exp2f throughout. CTA = 128 q rows x (b,h), 8 warps x 16 rows,
// K-tiles of 64 keys, 3-stage K/V ring (one __syncthreads per tile).
// P fp16 reused directly as A-frags. smem pitch 144B.
// ---------------------------------------------------------------------------
#define FPB 144
#define FL_KV 18432                  // Q tile: 128*144
#define FL_TILE 9216                 // one 64-row K or V tile
#define FL_BUF 18432                 // K | V per stage
#define FLASH2_SMEM (FL_KV + 3 * FL_BUF)   // 73728

__device__ __forceinline__ void fl_load_kv(uint32_t sb, const __half* base,
                                           int kt, int bi, int tid) {
    uint32_t dst0 = sb + FL_KV + bi * FL_BUF;
    #pragma unroll
    for (int it = 0; it < 4; it++) {
        int idx = tid + it * 256;
        int reg = idx >> 9;                  // 0 K, 1 V
        int r = idx & 511;
        int row = r >> 3, c = r & 7;
        const __half* s = base + (size_t)(kt * 64 + row) * QKVN + DD + reg * DD + c * 8;
        cp16(dst0 + reg * FL_TILE + row * FPB + c * 16, s);
    }
    CP_COMMIT();
}

__global__ __launch_bounds__(256, 2)
void flash2(const __half* __restrict__ qkv, __half* __restrict__ z) {
    extern __shared__ char sm[];
    const uint32_t sb = smem_u32(sm);
    const int tid = threadIdx.x, wid = tid >> 5, lid = tid & 31;
    const int qt = (int)gridDim.x - 1 - (int)blockIdx.x;   // heavy tiles first
    const int h = blockIdx.y, b = blockIdx.z;

    const __half* base = qkv + (size_t)b * SS * QKVN + h * 64;
    const int nkt = 2 * qt + 2;

    #pragma unroll
    for (int it = 0; it < 4; it++) {
        int idx = tid + it * 256;
        int row = idx >> 3, c = idx & 7;
        cp16(sb + row * FPB + c * 16, base + (size_t)(qt * 128 + row) * QKVN + c * 8);
    }
    CP_COMMIT();
    fl_load_kv(sb, base, 0, 0, tid);
    fl_load_kv(sb, base, 1, 1, tid);

    asm volatile("cp.async.wait_group 2;" ::: "memory");
    __syncthreads();

    const int g2 = lid >> 3, li = lid & 7;
    const int a_row = (g2 & 1) * 8 + li, a_kb = (g2 >> 1) * 16;
    const uint32_t qa = sb + (wid * 16 + a_row) * FPB + a_kb;
    uint32_t qh[4][4];
    #pragma unroll
    for (int kc = 0; kc < 4; kc++)
        ldsm4(qh[kc][0], qh[kc][1], qh[kc][2], qh[kc][3], qa + kc * 32);

    float o[8][4];
    #pragma unroll
    for (int nt = 0; nt < 8; nt++)
        #pragma unroll
        for (int e = 0; e < 4; e++) o[nt][e] = 0.f;
    float m0 = -1e30f, m1 = -1e30f, l0 = 0.f, l1 = 0.f;

    const int gq = lid >> 2, t4 = lid & 3;
    const int row0g = qt * 128 + wid * 16 + gq;
    const int row1g = row0g + 8;

    const uint32_t kb_off = (uint32_t)(((g2 >> 1) * 8 + li) * FPB + (g2 & 1) * 16);
    const uint32_t v_off  = (uint32_t)(((g2 & 1) * 8 + li) * FPB + (g2 >> 1) * 16);

    int bufsel = 0;
    for (int kt = 0; kt < nkt; kt++) {
        if (kt + 1 < nkt) { asm volatile("cp.async.wait_group 1;" ::: "memory"); }
        else              { asm volatile("cp.async.wait_group 0;" ::: "memory"); }
        __syncthreads();

        if (kt + 2 < nkt) {
            int nb = bufsel + 2; if (nb >= 3) nb -= 3;
            fl_load_kv(sb, base, kt + 2, nb, tid);
        }

        const uint32_t buf = sb + FL_KV + bufsel * FL_BUF;

        float s[8][4];
        #pragma unroll
        for (int nt = 0; nt < 8; nt++)
            #pragma unroll
            for (int e = 0; e < 4; e++) s[nt][e] = 0.f;

        #pragma unroll
        for (int kc = 0; kc < 4; kc++) {
            #pragma unroll
            for (int ntp = 0; ntp < 4; ntp++) {
                uint32_t ka = buf + kb_off + ntp * 16 * FPB + kc * 32;
                uint32_t h0, h1, h2, h3;
                ldsm4(h0, h1, h2, h3, ka);
                mma2(s[2 * ntp],     qh[kc], h0, h1);
                mma2(s[2 * ntp + 1], qh[kc], h2, h3);
            }
        }

        if (kt >= 2 * qt) {
            int colb = kt * 64 + 2 * t4;
            #pragma unroll
            for (int nt = 0; nt < 8; nt++) {
                int c0 = colb + nt * 8, c1 = c0 + 1;
                if (c0 > row0g) s[nt][0] = -1e30f;
                if (c1 > row0g) s[nt][1] = -1e30f;
                if (c0 > row1g) s[nt][2] = -1e30f;
                if (c1 > row1g) s[nt][3] = -1e30f;
            }
        }

        float tm0 = -1e30f, tm1 = -1e30f;
        #pragma unroll
        for (int nt = 0; nt < 8; nt++) {
            tm0 = fmaxf(tm0, fmaxf(s[nt][0], s[nt][1]));
            tm1 = fmaxf(tm1, fmaxf(s[nt][2], s[nt][3]));
        }
        tm0 = fmaxf(tm0, __shfl_xor_sync(0xffffffffu, tm0, 1));
        tm0 = fmaxf(tm0, __shfl_xor_sync(0xffffffffu, tm0, 2));
        tm1 = fmaxf(tm1, __shfl_xor_sync(0xffffffffu, tm1, 1));
        tm1 = fmaxf(tm1, __shfl_xor_sync(0xffffffffu, tm1, 2));
        float mn0 = fmaxf(m0, tm0), mn1 = fmaxf(m1, tm1);
        float al0 = exp2f(m0 - mn0), al1 = exp2f(m1 - mn1);
        m0 = mn0; m1 = mn1;

        float rs0 = 0.f, rs1 = 0.f;
        #pragma unroll
        for (int nt = 0; nt < 8; nt++) {
            s[nt][0] = exp2f(s[nt][0] - mn0); rs0 += s[nt][0];
            s[nt][1] = exp2f(s[nt][1] - mn0); rs0 += s[nt][1];
            s[nt][2] = exp2f(s[nt][2] - mn1); rs1 += s[nt][2];
            s[nt][3] = exp2f(s[nt][3] - mn1); rs1 += s[nt][3];
        }
        rs0 += __shfl_xor_sync(0xffffffffu, rs0, 1);
        rs0 += __shfl_xor_sync(0xffffffffu, rs0, 2);
        rs1 += __shfl_xor_sync(0xffffffffu, rs1, 1);
        rs1 += __shfl_xor_sync(0xffffffffu, rs1, 2);
        l0 = l0 * al0 + rs0;
        l1 = l1 * al1 + rs1;
        #pragma unroll
        for (int nt = 0; nt < 8; nt++) {
            o[nt][0] *= al0; o[nt][1] *= al0;
            o[nt][2] *= al1; o[nt][3] *= al1;
        }

        uint32_t pa[4][4];
        #pragma unroll
        for (int kc = 0; kc < 4; kc++) {
            pa[kc][0] = f2h2(s[2 * kc][0],     s[2 * kc][1]);
            pa[kc][1] = f2h2(s[2 * kc][2],     s[2 * kc][3]);
            pa[kc][2] = f2h2(s[2 * kc + 1][0], s[2 * kc + 1][1]);
            pa[kc][3] = f2h2(s[2 * kc + 1][2], s[2 * kc + 1][3]);
        }

        #pragma unroll
        for (int kc = 0; kc < 4; kc++) {
            #pragma unroll
            for (int ntp = 0; ntp < 4; ntp++) {
                uint32_t va = buf + FL_TILE + kc * 16 * FPB + ntp * 32 + v_off;
                uint32_t h0, h1, h2, h3;
                ldsm4t(h0, h1, h2, h3, va);
                mma2(o[2 * ntp],     pa[kc], h0, h1);
                mma2(o[2 * ntp + 1], pa[kc], h2, h3);
            }
        }
        if (++bufsel == 3) bufsel = 0;
    }

    float iv0 = 1.f / l0, iv1 = 1.f / l1;
    size_t r0 = (size_t)b * SS + qt * 128 + wid * 16 + gq;
    size_t r1 = r0 + 8;
    #pragma unroll
    for (int nt = 0; nt < 8; nt++) {
        int col = h * 64 + nt * 8 + 2 * t4;
        *(__half2*)(z + r0 * DD + col) = __floats2half2_rn(o[nt][0] * iv0, o[nt][1] * iv0);
        *(__half2*)(z + r1 * DD + col) = __floats2half2_rn(o[nt][2] * iv1, o[nt][3] * iv1);
    }
}

// ---------------------------------------------------------------------------
// Launch
// ---------------------------------------------------------------------------
extern "C" void kernel_launch(void* const* d_in, const int* in_sizes, int n_in,
                              void* d_out, int out_size) {
    (void)in_sizes; (void)n_in; (void)out_size;
    const float* resid_pre = (const float*)d_in[0];
    const float* ln1_w = (const float*)d_in[1];
    const float* ln1_b = (const float*)d_in[2];
    const float* W_Q   = (const float*)d_in[3];
    const float* W_K   = (const float*)d_in[4];
    const float* W_V   = (const float*)d_in[5];
    const float* W_O   = (const float*)d_in[6];
    const float* b_Q   = (const float*)d_in[7];
    const float* b_K   = (const float*)d_in[8];
    const float* b_V   = (const float*)d_in[9];
    const float* b_O   = (const float*)d_in[10];
    const float* ln2_w = (const float*)d_in[11];
    const float* ln2_b = (const float*)d_in[12];
    const float* W_in  = (const float*)d_in[13];
    const float* b_in  = (const float*)d_in[14];
    const float* W_out = (const float*)d_in[15];
    const float* b_out = (const float*)d_in[16];
    float* out = (float*)d_out;

    __half *p_x1, *p_wqkv, *p_qkv, *p_z, *p_wo, *p_x2, *p_win, *p_h, *p_wout;
    float *p_bqkv, *p_rmid;
    cudaGetSymbolAddress((void**)&p_x1, g_x1);
    cudaGetSymbolAddress((void**)&p_wqkv, g_wqkv);
    cudaGetSymbolAddress((void**)&p_bqkv, g_bqkv);
    cudaGetSymbolAddress((void**)&p_qkv, g_qkv);
    cudaGetSymbolAddress((void**)&p_z, g_z);
    cudaGetSymbolAddress((void**)&p_wo, g_wo);
    cudaGetSymbolAddress((void**)&p_rmid, g_rmid);
    cudaGetSymbolAddress((void**)&p_x2, g_x2);
    cudaGetSymbolAddress((void**)&p_win, g_win);
    cudaGetSymbolAddress((void**)&p_h, g_h);
    cudaGetSymbolAddress((void**)&p_wout, g_wout);

    cudaFuncSetAttribute(flash2, cudaFuncAttributeMaxDynamicSharedMemorySize, FLASH2_SMEM);
    cudaFuncSetAttribute(gemm_hmma<1>, cudaFuncAttributeMaxDynamicSharedMemorySize, GEMM_SMEM);
    cudaFuncSetAttribute(gemm_hmma<2>, cudaFuncAttributeMaxDynamicSharedMemorySize, GEMM_SMEM);
    cudaFuncSetAttribute(gemm_hmma<3>, cudaFuncAttributeMaxDynamicSharedMemorySize, GEMM_SMEM);

    // ALL prep (weight conversions + bias pack + LN1) in one launch
    prep_kernel<<<PREP_BLOCKS, 256>>>(W_Q, W_K, W_V, b_Q, b_K, b_V,
                                      W_O, W_in, W_out,
                                      resid_pre, ln1_w, ln1_b);

    // QKV projection -> fp16 (Q scaled by 0.125*log2e)
    gemm_hmma<3><<<dim3(QKVN / 64, BSS / 128), 256, GEMM_SMEM>>>(
        p_x1, p_wqkv, p_bqkv, nullptr, nullptr, p_qkv, BSS, QKVN, DD);

    // flash attention (tensor cores, base-2 softmax) -> z
    flash2<<<dim3(SS / 128, HH, BB), 256, FLASH2_SMEM>>>(p_qkv, p_z);

    // O projection + residual -> rmid fp32
    gemm_hmma<2><<<dim3(DD / 64, BSS / 128), 256, GEMM_SMEM>>>(
        p_z, p_wo, b_O, resid_pre, p_rmid, nullptr, BSS, DD, DD);

    // LN2
    ln_kernel<<<BSS, 256>>>(p_rmid, ln2_w, ln2_b, p_x2);

    // MLP in + gelu -> h fp16
    gemm_hmma<1><<<dim3(DMM / 64, BSS / 128), 256, GEMM_SMEM>>>(
        p_x2, p_win, b_in, nullptr, nullptr, p_h, BSS, DMM, DD);

    // MLP out + residual -> out fp32
    gemm_hmma<2><<<dim3(DD / 64, BSS / 128), 256, GEMM_SMEM>>>(
        p_h, p_wout, b_out, p_rmid, out, nullptr, BSS, DD, DMM);
}

// round 13
// speedup vs baseline: 1.1055x; 1.1055x over previous
#include <cuda_runtime.h>
#include <cuda_fp16.h>
#include <cstdint>
#include <cstddef>

// ---------------------------------------------------------------------------
// Problem constants
// ---------------------------------------------------------------------------
#define BB   2
#define SS   2048
#define DD   1024
#define HH   16
#define DHH  64
#define DMM  4096
#define BSS  (BB * SS)          // 4096 rows
#define QKVN (3 * DD)           // 3072
#define LN_EPS 1e-5f
#define LOG2E 1.4426950408889634f

// ---------------------------------------------------------------------------
// Scratch (static device globals; fp16 single-precision path, fp32 accum)
// ---------------------------------------------------------------------------
__device__ __half g_x1[BSS * DD];                 // LN1 out
__device__ __half g_wqkv[QKVN * DD];              // [N=3072,K=1024]
__device__ float  g_bqkv[QKVN];
__device__ __half g_qkv[(size_t)BSS * QKVN];      // q(0.125*log2e-folded)|k|v
__device__ __half g_z[BSS * DD];                  // attention out
__device__ __half g_wo[DD * DD];                  // [N=1024,K=1024]
__device__ float  g_rmid[BSS * DD];
__device__ __half g_x2[BSS * DD];                 // LN2 out
__device__ __half g_win[DMM * DD];                // [N=4096,K=1024]
__device__ __half g_h[(size_t)BSS * DMM];         // MLP hidden
__device__ __half g_wout[DD * DMM];               // [N=1024,K=4096]

// ---------------------------------------------------------------------------
// PTX helpers (baseline ISA: ldmatrix / mma.sync / cp.async)
// ---------------------------------------------------------------------------
__device__ __forceinline__ uint32_t smem_u32(const void* p) {
    uint32_t a;
    asm("{ .reg .u64 t; cvta.to.shared.u64 t, %1; cvt.u32.u64 %0, t; }" : "=r"(a) : "l"(p));
    return a;
}
__device__ __forceinline__ void ldsm4(uint32_t& r0, uint32_t& r1, uint32_t& r2,
                                      uint32_t& r3, uint32_t a) {
    asm volatile("ldmatrix.sync.aligned.m8n8.x4.shared.b16 {%0,%1,%2,%3}, [%4];"
                 : "=r"(r0), "=r"(r1), "=r"(r2), "=r"(r3) : "r"(a));
}
__device__ __forceinline__ void ldsm4t(uint32_t& r0, uint32_t& r1, uint32_t& r2,
                                       uint32_t& r3, uint32_t a) {
    asm volatile("ldmatrix.sync.aligned.m8n8.x4.trans.shared.b16 {%0,%1,%2,%3}, [%4];"
                 : "=r"(r0), "=r"(r1), "=r"(r2), "=r"(r3) : "r"(a));
}
__device__ __forceinline__ void mma16816(float* c, const uint32_t* a, const uint32_t* b) {
    asm volatile(
        "mma.sync.aligned.m16n8k16.row.col.f32.f16.f16.f32 "
        "{%0,%1,%2,%3},{%4,%5,%6,%7},{%8,%9},{%0,%1,%2,%3};"
        : "+f"(c[0]), "+f"(c[1]), "+f"(c[2]), "+f"(c[3])
        : "r"(a[0]), "r"(a[1]), "r"(a[2]), "r"(a[3]), "r"(b[0]), "r"(b[1]));
}
__device__ __forceinline__ void mma2(float* c, const uint32_t* a, uint32_t b0, uint32_t b1) {
    asm volatile(
        "mma.sync.aligned.m16n8k16.row.col.f32.f16.f16.f32 "
        "{%0,%1,%2,%3},{%4,%5,%6,%7},{%8,%9},{%0,%1,%2,%3};"
        : "+f"(c[0]), "+f"(c[1]), "+f"(c[2]), "+f"(c[3])
        : "r"(a[0]), "r"(a[1]), "r"(a[2]), "r"(a[3]), "r"(b0), "r"(b1));
}
__device__ __forceinline__ void cp16(uint32_t d, const void* s) {
    asm volatile("cp.async.cg.shared.global [%0], [%1], 16;" :: "r"(d), "l"(s) : "memory");
}
#define CP_COMMIT() asm volatile("cp.async.commit_group;" ::: "memory")

__device__ __forceinline__ uint32_t f2h2(float a, float b) {
    __half2 h = __floats2half2_rn(a, b);
    return *(uint32_t*)&h;
}

// ---------------------------------------------------------------------------
// Block reduction
// ---------------------------------------------------------------------------
__device__ __forceinline__ float block_sum(float v, float* red) {
    __syncthreads();
    int lane = threadIdx.x & 31, wid = threadIdx.x >> 5;
    #pragma unroll
    for (int o = 16; o > 0; o >>= 1) v += __shfl_xor_sync(0xffffffffu, v, o);
    if (lane == 0) red[wid] = v;
    __syncthreads();
    float t = (threadIdx.x < (blockDim.x >> 5)) ? red[threadIdx.x] : 0.f;
    if (wid == 0) {
        #pragma unroll
        for (int o = 16; o > 0; o >>= 1) t += __shfl_xor_sync(0xffffffffu, t, o);
        if (lane == 0) red[0] = t;
    }
    __syncthreads();
    return red[0];
}

// ---------------------------------------------------------------------------
// LN row body (register-resident, 256 threads x float4)
// ---------------------------------------------------------------------------
__device__ __forceinline__ void ln_body(const float* __restrict__ x,
                                        const float* __restrict__ w,
                                        const float* __restrict__ b,
                                        __half* __restrict__ o, int r, float* red) {
    int tid = threadIdx.x;
    float4 v = ((const float4*)(x + (size_t)r * DD))[tid];
    float s = block_sum(v.x + v.y + v.z + v.w, red);
    float mean = s * (1.f / DD);
    float dx = v.x - mean, dy = v.y - mean, dz = v.z - mean, dw = v.w - mean;
    float q = block_sum(dx * dx + dy * dy + dz * dz + dw * dw, red);
    float inv = rsqrtf(q * (1.f / DD) + LN_EPS);
    float4 w4 = ((const float4*)w)[tid];
    float4 b4 = ((const float4*)b)[tid];
    __half2 h0 = __floats2half2_rn(dx * inv * w4.x + b4.x, dy * inv * w4.y + b4.y);
    __half2 h1 = __floats2half2_rn(dz * inv * w4.z + b4.z, dw * inv * w4.w + b4.w);
    uint2 pk; pk.x = *(uint32_t*)&h0; pk.y = *(uint32_t*)&h1;
    ((uint2*)(o + (size_t)r * DD))[tid] = pk;
}

// conv_wT body: W fp32 [K,N] tile -> B fp16 [N,K]
__device__ __forceinline__ void wT_body(const float* __restrict__ W,
                                        __half* __restrict__ B, int K, int N,
                                        int n0, int k0, float* t /*32x33*/) {
    int tid = threadIdx.x;
    int tx = tid & 31, ty = tid >> 5;   // ty 0..7
    #pragma unroll
    for (int i = 0; i < 4; i++)
        t[(ty + i * 8) * 33 + tx] = W[(size_t)(k0 + ty + i * 8) * N + n0 + tx];
    __syncthreads();
    #pragma unroll
    for (int i = 0; i < 4; i++) {
        int n = n0 + ty + i * 8, k = k0 + tx;
        B[(size_t)n * K + k] = __float2half_rn(t[tx * 33 + ty + i * 8]);
    }
}

// ---------------------------------------------------------------------------
// prep_kernel: ALL weight conversions + bias pack + LN1 in ONE launch.
// ---------------------------------------------------------------------------
#define PREP_BLOCKS 13828

__global__ __launch_bounds__(256)
void prep_kernel(const float* __restrict__ WQ, const float* __restrict__ WK,
                 const float* __restrict__ WV, const float* __restrict__ bQ,
                 const float* __restrict__ bK, const float* __restrict__ bV,
                 const float* __restrict__ WO, const float* __restrict__ Win,
                 const float* __restrict__ Wout, const float* __restrict__ resid,
                 const float* __restrict__ ln1w, const float* __restrict__ ln1b) {
    __shared__ float smf[32 * 65];
    int bid = blockIdx.x;
    int tid = threadIdx.x;

    if (bid < 4096) {
        int n0 = (bid & 127) * 32, k0 = (bid >> 7) * 32;
        wT_body(Win, g_win, DD, DMM, n0, k0, smf);
        return;
    }
    bid -= 4096;
    if (bid < 4096) {
        int n0 = (bid & 31) * 32, k0 = (bid >> 5) * 32;
        wT_body(Wout, g_wout, DMM, DD, n0, k0, smf);
        return;
    }
    bid -= 4096;
    if (bid < 4096) {
        ln_body(resid, ln1w, ln1b, g_x1, bid, smf);
        return;
    }
    bid -= 4096;
    if (bid < 1024) {
        int n0 = (bid & 31) * 32, k0 = (bid >> 5) * 32;
        wT_body(WO, g_wo, DD, DD, n0, k0, smf);
        return;
    }
    bid -= 1024;
    if (bid < 512) {
        int k0 = (bid & 31) * 32, h = bid >> 5;
        const float* Ws[3] = {WQ, WK, WV};
        for (int s = 0; s < 3; s++) {
            const float* src = Ws[s] + (size_t)h * DD * DHH + (size_t)k0 * DHH;
            #pragma unroll
            for (int it = 0; it < 8; it++) {
                int idx = tid + it * 256;
                smf[(idx >> 6) * 65 + (idx & 63)] = src[idx];
            }
            __syncthreads();
            #pragma unroll
            for (int it = 0; it < 8; it++) {
                int idx = tid + it * 256;
                int dh = idx >> 5, kk = idx & 31;
                size_t n = (size_t)s * DD + h * 64 + dh;
                g_wqkv[n * DD + k0 + kk] = __float2half_rn(smf[kk * 65 + dh]);
            }
            __syncthreads();
        }
        return;
    }
    bid -= 512;
    {
        int i = bid * 256 + tid;
        g_bqkv[i]          = bQ[i];
        g_bqkv[DD + i]     = bK[i];
        g_bqkv[2 * DD + i] = bV[i];
    }
}

__device__ __forceinline__ float gelu_tanh(float x) {
    float x3 = x * x * x;
    return 0.5f * x * (1.f + tanhf(0.7978845608028654f * (x + 0.044715f * x3)));
}

// ---------------------------------------------------------------------------
// LN2 (standalone; depends on rmid)
// ---------------------------------------------------------------------------
__global__ __launch_bounds__(256)
void ln_kernel(const float* __restrict__ x, const float* __restrict__ w,
               const float* __restrict__ b, __half* __restrict__ o) {
    __shared__ float red[32];
    ln_body(x, w, b, o, blockIdx.x, red);
}

// ---------------------------------------------------------------------------
// HMMA fp16 GEMM: C = A @ B^T + bias ; fp32 accumulate.
// 128x128 CTA tile, 256 threads, 8 warps (2x4), warp tile 64x32, K-tile 64.
// 3-STAGE cp.async ring, ONE __syncthreads/iter, prefetch issued BEFORE
// compute -> ~2 iterations (~1300 cyc) of load-latency cover (R11 profile
// showed wait_group stalls: 4000 cyc/iter vs ~600 issue).
// 144B smem pitch (conflict-free). 2 CTAs/SM (2x110592 = 216KB smem).
// EPI: 1 bias+gelu -> fp16 ; 2 bias+residual -> fp32 ; 3 bias (Q cols *0.125*log2e) -> fp16
// ---------------------------------------------------------------------------
#define GOPD 18432                   // 128 rows * 144 B
#define GBUF (2 * GOPD)              // A | B per stage: 36864
#define GEMM_SMEM (3 * GBUF)         // 3-stage ring: 110592

__device__ __forceinline__ void gemm_load(uint32_t dst, const char* const* src,
                                          size_t rowB, int k0b, int tid) {
    #pragma unroll
    for (int it = 0; it < 8; it++) {
        int c = tid + it * 256;
        int o = c >> 10, r = c & 1023, row = r >> 3, kc = r & 7;
        cp16(dst + o * GOPD + row * 144 + kc * 16,
             src[o] + (size_t)row * rowB + k0b + kc * 16);
    }
    CP_COMMIT();
}

template <int EPI>
__global__ __launch_bounds__(256, 2)
void gemm_hmma(const __half* __restrict__ A, const __half* __restrict__ B,
               const float* __restrict__ bias, const float* __restrict__ R,
               float* __restrict__ Cf, __half* __restrict__ Ch,
               int M, int N, int K) {
    extern __shared__ char sm[];
    const uint32_t sb = smem_u32(sm);
    const int tid = threadIdx.x;
    const int wid = tid >> 5, lid = tid & 31;
    const int warp_m = wid >> 2, warp_n = wid & 3;

    const char* src[2];
    src[0] = (const char*)(A + (size_t)blockIdx.y * 128 * K);
    src[1] = (const char*)(B + (size_t)blockIdx.x * 128 * K);
    const size_t rowB = (size_t)K * 2;

    const int g = lid >> 3, li = lid & 7;
    const int a_row = (g & 1) * 8 + li, a_kb = (g >> 1) * 16;
    const int b_row = (g >> 1) * 8 + li, b_kb = (g & 1) * 16;

    float acc[4][4][4];
    #pragma unroll
    for (int mt = 0; mt < 4; mt++)
        #pragma unroll
        for (int nt = 0; nt < 4; nt++)
            #pragma unroll
            for (int e = 0; e < 4; e++) acc[mt][nt][e] = 0.f;

    const int T = K >> 6;   // K-tiles of 64

    // prologue: stage tiles 0, 1
    gemm_load(sb, src, rowB, 0, tid);
    gemm_load(sb + GBUF, src, rowB, 128, tid);

    int sel = 0;   // t % 3
    for (int t = 0; t < T; t++) {
        if (t + 1 < T) { asm volatile("cp.async.wait_group 1;" ::: "memory"); }
        else           { asm volatile("cp.async.wait_group 0;" ::: "memory"); }
        __syncthreads();

        // prefetch tile t+2 FIRST (slot (t+2)%3 was consumed in iter t-1;
        // this barrier proves consumption finished)
        if (t + 2 < T) {
            int nb = sel + 2; if (nb >= 3) nb -= 3;
            gemm_load(sb + nb * GBUF, src, rowB, (t + 2) * 128, tid);
        }

        uint32_t buf = sb + sel * GBUF;
        uint32_t aP = buf + (warp_m * 64 + a_row) * 144 + a_kb;
        uint32_t bP = buf + GOPD + (warp_n * 32 + b_row) * 144 + b_kb;

        #pragma unroll
        for (int kk = 0; kk < 4; kk++) {
            uint32_t bh[4][2];
            ldsm4(bh[0][0], bh[0][1], bh[1][0], bh[1][1], bP + kk * 32);
            ldsm4(bh[2][0], bh[2][1], bh[3][0], bh[3][1], bP + 16 * 144 + kk * 32);
            #pragma unroll
            for (int mt = 0; mt < 4; mt++) {
                uint32_t ah[4];
                ldsm4(ah[0], ah[1], ah[2], ah[3], aP + mt * 16 * 144 + kk * 32);
                #pragma unroll
                for (int nt = 0; nt < 4; nt++)
                    mma16816(acc[mt][nt], ah, bh[nt]);
            }
        }
        if (++sel == 3) sel = 0;
    }

    const int group = lid >> 2, t4 = lid & 3;
    const size_t rbase = (size_t)blockIdx.y * 128 + warp_m * 64;
    const int cbase = blockIdx.x * 128 + warp_n * 32;
    #pragma unroll
    for (int mt = 0; mt < 4; mt++) {
        size_t r0 = rbase + mt * 16 + group;
        size_t r1 = r0 + 8;
        #pragma unroll
        for (int nt = 0; nt < 4; nt++) {
            int col = cbase + nt * 8 + t4 * 2;
            float* c = acc[mt][nt];
            float b0 = bias[col], b1 = bias[col + 1];
            float x0 = c[0] + b0, x1 = c[1] + b1;
            float x2 = c[2] + b0, x3 = c[3] + b1;
            if (EPI == 1 || EPI == 3) {
                if (EPI == 1) {
                    x0 = gelu_tanh(x0); x1 = gelu_tanh(x1);
                    x2 = gelu_tanh(x2); x3 = gelu_tanh(x3);
                } else {
                    // fold 1/sqrt(DH) AND log2(e) into Q -> scores are base-2 logits
                    float qsc = (blockIdx.x < 8) ? 0.125f * LOG2E : 1.0f;
                    x0 *= qsc; x1 *= qsc; x2 *= qsc; x3 *= qsc;
                }
                *(__half2*)(Ch + r0 * N + col) = __floats2half2_rn(x0, x1);
                *(__half2*)(Ch + r1 * N + col) = __floats2half2_rn(x2, x3);
            } else {
                float2 ra = *(const float2*)(R + r0 * N + col);
                float2 rb = *(const float2*)(R + r1 * N + col);
                x0 += ra.x; x1 += ra.y; x2 += rb.x; x3 += rb.y;
                float2 va; va.x = x0; va.y = x1;
                float2 vb; vb.x = x2; vb.y = x3;
                *(float2*)(Cf + r0 * N + col) = va;
                *(float2*)(Cf + r1 * N + col) = vb;
            }
        }
    }
}

// ---------------------------------------------------------------------------
// flash2: tensor-core causal flash attention. Base-2 softmax (log2e folded
// into Q), exp2f throughout. CTA = 128 q rows x (b,h), 8 warps x 16 rows,
// K-tiles of 64 keys, 3-stage K/V ring (one __syncthreads per tile).
// P fp16 reused directly as A-frags. smem pitch 144B.
// ---------------------------------------------------------------------------
#define FPB 144
#define FL_KV 18432                  // Q tile: 128*144
#define FL_TILE 9216                 // one 64-row K or V tile
#define FL_BUF 18432                 // K | V per stage
#define FLASH2_SMEM (FL_KV + 3 * FL_BUF)   // 73728

__device__ __forceinline__ void fl_load_kv(uint32_t sb, const __half* base,
                                           int kt, int bi, int tid) {
    uint32_t dst0 = sb + FL_KV + bi * FL_BUF;
    #pragma unroll
    for (int it = 0; it < 4; it++) {
        int idx = tid + it * 256;
        int reg = idx >> 9;                  // 0 K, 1 V
        int r = idx & 511;
        int row = r >> 3, c = r & 7;
        const __half* s = base + (size_t)(kt * 64 + row) * QKVN + DD + reg * DD + c * 8;
        cp16(dst0 + reg * FL_TILE + row * FPB + c * 16, s);
    }
    CP_COMMIT();
}

__global__ __launch_bounds__(256, 2)
void flash2(const __half* __restrict__ qkv, __half* __restrict__ z) {
    extern __shared__ char sm[];
    const uint32_t sb = smem_u32(sm);
    const int tid = threadIdx.x, wid = tid >> 5, lid = tid & 31;
    const int qt = (int)gridDim.x - 1 - (int)blockIdx.x;   // heavy tiles first
    const int h = blockIdx.y, b = blockIdx.z;

    const __half* base = qkv + (size_t)b * SS * QKVN + h * 64;
    const int nkt = 2 * qt + 2;

    #pragma unroll
    for (int it = 0; it < 4; it++) {
        int idx = tid + it * 256;
        int row = idx >> 3, c = idx & 7;
        cp16(sb + row * FPB + c * 16, base + (size_t)(qt * 128 + row) * QKVN + c * 8);
    }
    CP_COMMIT();
    fl_load_kv(sb, base, 0, 0, tid);
    fl_load_kv(sb, base, 1, 1, tid);

    asm volatile("cp.async.wait_group 2;" ::: "memory");
    __syncthreads();

    const int g2 = lid >> 3, li = lid & 7;
    const int a_row = (g2 & 1) * 8 + li, a_kb = (g2 >> 1) * 16;
    const uint32_t qa = sb + (wid * 16 + a_row) * FPB + a_kb;
    uint32_t qh[4][4];
    #pragma unroll
    for (int kc = 0; kc < 4; kc++)
        ldsm4(qh[kc][0], qh[kc][1], qh[kc][2], qh[kc][3], qa + kc * 32);

    float o[8][4];
    #pragma unroll
    for (int nt = 0; nt < 8; nt++)
        #pragma unroll
        for (int e = 0; e < 4; e++) o[nt][e] = 0.f;
    float m0 = -1e30f, m1 = -1e30f, l0 = 0.f, l1 = 0.f;

    const int gq = lid >> 2, t4 = lid & 3;
    const int row0g = qt * 128 + wid * 16 + gq;
    const int row1g = row0g + 8;

    const uint32_t kb_off = (uint32_t)(((g2 >> 1) * 8 + li) * FPB + (g2 & 1) * 16);
    const uint32_t v_off  = (uint32_t)(((g2 & 1) * 8 + li) * FPB + (g2 >> 1) * 16);

    int bufsel = 0;
    for (int kt = 0; kt < nkt; kt++) {
        if (kt + 1 < nkt) { asm volatile("cp.async.wait_group 1;" ::: "memory"); }
        else              { asm volatile("cp.async.wait_group 0;" ::: "memory"); }
        __syncthreads();

        if (kt + 2 < nkt) {
            int nb = bufsel + 2; if (nb >= 3) nb -= 3;
            fl_load_kv(sb, base, kt + 2, nb, tid);
        }

        const uint32_t buf = sb + FL_KV + bufsel * FL_BUF;

        float s[8][4];
        #pragma unroll
        for (int nt = 0; nt < 8; nt++)
            #pragma unroll
            for (int e = 0; e < 4; e++) s[nt][e] = 0.f;

        #pragma unroll
        for (int kc = 0; kc < 4; kc++) {
            #pragma unroll
            for (int ntp = 0; ntp < 4; ntp++) {
                uint32_t ka = buf + kb_off + ntp * 16 * FPB + kc * 32;
                uint32_t h0, h1, h2, h3;
                ldsm4(h0, h1, h2, h3, ka);
                mma2(s[2 * ntp],     qh[kc], h0, h1);
                mma2(s[2 * ntp + 1], qh[kc], h2, h3);
            }
        }

        if (kt >= 2 * qt) {
            int colb = kt * 64 + 2 * t4;
            #pragma unroll
            for (int nt = 0; nt < 8; nt++) {
                int c0 = colb + nt * 8, c1 = c0 + 1;
                if (c0 > row0g) s[nt][0] = -1e30f;
                if (c1 > row0g) s[nt][1] = -1e30f;
                if (c0 > row1g) s[nt][2] = -1e30f;
                if (c1 > row1g) s[nt][3] = -1e30f;
            }
        }

        float tm0 = -1e30f, tm1 = -1e30f;
        #pragma unroll
        for (int nt = 0; nt < 8; nt++) {
            tm0 = fmaxf(tm0, fmaxf(s[nt][0], s[nt][1]));
            tm1 = fmaxf(tm1, fmaxf(s[nt][2], s[nt][3]));
        }
        tm0 = fmaxf(tm0, __shfl_xor_sync(0xffffffffu, tm0, 1));
        tm0 = fmaxf(tm0, __shfl_xor_sync(0xffffffffu, tm0, 2));
        tm1 = fmaxf(tm1, __shfl_xor_sync(0xffffffffu, tm1, 1));
        tm1 = fmaxf(tm1, __shfl_xor_sync(0xffffffffu, tm1, 2));
        float mn0 = fmaxf(m0, tm0), mn1 = fmaxf(m1, tm1);
        float al0 = exp2f(m0 - mn0), al1 = exp2f(m1 - mn1);
        m0 = mn0; m1 = mn1;

        float rs0 = 0.f, rs1 = 0.f;
        #pragma unroll
        for (int nt = 0; nt < 8; nt++) {
            s[nt][0] = exp2f(s[nt][0] - mn0); rs0 += s[nt][0];
            s[nt][1] = exp2f(s[nt][1] - mn0); rs0 += s[nt][1];
            s[nt][2] = exp2f(s[nt][2] - mn1); rs1 += s[nt][2];
            s[nt][3] = exp2f(s[nt][3] - mn1); rs1 += s[nt][3];
        }
        rs0 += __shfl_xor_sync(0xffffffffu, rs0, 1);
        rs0 += __shfl_xor_sync(0xffffffffu, rs0, 2);
        rs1 += __shfl_xor_sync(0xffffffffu, rs1, 1);
        rs1 += __shfl_xor_sync(0xffffffffu, rs1, 2);
        l0 = l0 * al0 + rs0;
        l1 = l1 * al1 + rs1;
        #pragma unroll
        for (int nt = 0; nt < 8; nt++) {
            o[nt][0] *= al0; o[nt][1] *= al0;
            o[nt][2] *= al1; o[nt][3] *= al1;
        }

        uint32_t pa[4][4];
        #pragma unroll
        for (int kc = 0; kc < 4; kc++) {
            pa[kc][0] = f2h2(s[2 * kc][0],     s[2 * kc][1]);
            pa[kc][1] = f2h2(s[2 * kc][2],     s[2 * kc][3]);
            pa[kc][2] = f2h2(s[2 * kc + 1][0], s[2 * kc + 1][1]);
            pa[kc][3] = f2h2(s[2 * kc + 1][2], s[2 * kc + 1][3]);
        }

        #pragma unroll
        for (int kc = 0; kc < 4; kc++) {
            #pragma unroll
            for (int ntp = 0; ntp < 4; ntp++) {
                uint32_t va = buf + FL_TILE + kc * 16 * FPB + ntp * 32 + v_off;
                uint32_t h0, h1, h2, h3;
                ldsm4t(h0, h1, h2, h3, va);
                mma2(o[2 * ntp],     pa[kc], h0, h1);
                mma2(o[2 * ntp + 1], pa[kc], h2, h3);
            }
        }
        if (++bufsel == 3) bufsel = 0;
    }

    float iv0 = 1.f / l0, iv1 = 1.f / l1;
    size_t r0 = (size_t)b * SS + qt * 128 + wid * 16 + gq;
    size_t r1 = r0 + 8;
    #pragma unroll
    for (int nt = 0; nt < 8; nt++) {
        int col = h * 64 + nt * 8 + 2 * t4;
        *(__half2*)(z + r0 * DD + col) = __floats2half2_rn(o[nt][0] * iv0, o[nt][1] * iv0);
        *(__half2*)(z + r1 * DD + col) = __floats2half2_rn(o[nt][2] * iv1, o[nt][3] * iv1);
    }
}

// ---------------------------------------------------------------------------
// Launch
// ---------------------------------------------------------------------------
extern "C" void kernel_launch(void* const* d_in, const int* in_sizes, int n_in,
                              void* d_out, int out_size) {
    (void)in_sizes; (void)n_in; (void)out_size;
    const float* resid_pre = (const float*)d_in[0];
    const float* ln1_w = (const float*)d_in[1];
    const float* ln1_b = (const float*)d_in[2];
    const float* W_Q   = (const float*)d_in[3];
    const float* W_K   = (const float*)d_in[4];
    const float* W_V   = (const float*)d_in[5];
    const float* W_O   = (const float*)d_in[6];
    const float* b_Q   = (const float*)d_in[7];
    const float* b_K   = (const float*)d_in[8];
    const float* b_V   = (const float*)d_in[9];
    const float* b_O   = (const float*)d_in[10];
    const float* ln2_w = (const float*)d_in[11];
    const float* ln2_b = (const float*)d_in[12];
    const float* W_in  = (const float*)d_in[13];
    const float* b_in  = (const float*)d_in[14];
    const float* W_out = (const float*)d_in[15];
    const float* b_out = (const float*)d_in[16];
    float* out = (float*)d_out;

    __half *p_x1, *p_wqkv, *p_qkv, *p_z, *p_wo, *p_x2, *p_win, *p_h, *p_wout;
    float *p_bqkv, *p_rmid;
    cudaGetSymbolAddress((void**)&p_x1, g_x1);
    cudaGetSymbolAddress((void**)&p_wqkv, g_wqkv);
    cudaGetSymbolAddress((void**)&p_bqkv, g_bqkv);
    cudaGetSymbolAddress((void**)&p_qkv, g_qkv);
    cudaGetSymbolAddress((void**)&p_z, g_z);
    cudaGetSymbolAddress((void**)&p_wo, g_wo);
    cudaGetSymbolAddress((void**)&p_rmid, g_rmid);
    cudaGetSymbolAddress((void**)&p_x2, g_x2);
    cudaGetSymbolAddress((void**)&p_win, g_win);
    cudaGetSymbolAddress((void**)&p_h, g_h);
    cudaGetSymbolAddress((void**)&p_wout, g_wout);

    cudaFuncSetAttribute(flash2, cudaFuncAttributeMaxDynamicSharedMemorySize, FLASH2_SMEM);
    cudaFuncSetAttribute(gemm_hmma<1>, cudaFuncAttributeMaxDynamicSharedMemorySize, GEMM_SMEM);
    cudaFuncSetAttribute(gemm_hmma<2>, cudaFuncAttributeMaxDynamicSharedMemorySize, GEMM_SMEM);
    cudaFuncSetAttribute(gemm_hmma<3>, cudaFuncAttributeMaxDynamicSharedMemorySize, GEMM_SMEM);

    // ALL prep (weight conversions + bias pack + LN1) in one launch
    prep_kernel<<<PREP_BLOCKS, 256>>>(W_Q, W_K, W_V, b_Q, b_K, b_V,
                                      W_O, W_in, W_out,
                                      resid_pre, ln1_w, ln1_b);

    // QKV projection -> fp16 (Q scaled by 0.125*log2e)
    gemm_hmma<3><<<dim3(QKVN / 128, BSS / 128), 256, GEMM_SMEM>>>(
        p_x1, p_wqkv, p_bqkv, nullptr, nullptr, p_qkv, BSS, QKVN, DD);

    // flash attention (tensor cores, base-2 softmax) -> z
    flash2<<<dim3(SS / 128, HH, BB), 256, FLASH2_SMEM>>>(p_qkv, p_z);

    // O projection + residual -> rmid fp32
    gemm_hmma<2><<<dim3(DD / 128, BSS / 128), 256, GEMM_SMEM>>>(
        p_z, p_wo, b_O, resid_pre, p_rmid, nullptr, BSS, DD, DD);

    // LN2
    ln_kernel<<<BSS, 256>>>(p_rmid, ln2_w, ln2_b, p_x2);

    // MLP in + gelu -> h fp16
    gemm_hmma<1><<<dim3(DMM / 128, BSS / 128), 256, GEMM_SMEM>>>(
        p_x2, p_win, b_in, nullptr, nullptr, p_h, BSS, DMM, DD);

    // MLP out + residual -> out fp32
    gemm_hmma<2><<<dim3(DD / 128, BSS / 128), 256, GEMM_SMEM>>>(
        p_h, p_wout, b_out, p_rmid, out, nullptr, BSS, DD, DMM);
}

// round 14
// speedup vs baseline: 1.1562x; 1.0458x over previous
#include <cuda_runtime.h>
#include <cuda_fp16.h>
#include <cstdint>
#include <cstddef>

// ---------------------------------------------------------------------------
// Problem constants
// ---------------------------------------------------------------------------
#define BB   2
#define SS   2048
#define DD   1024
#define HH   16
#define DHH  64
#define DMM  4096
#define BSS  (BB * SS)          // 4096 rows
#define QKVN (3 * DD)           // 3072
#define LN_EPS 1e-5f
#define LOG2E 1.4426950408889634f

// ---------------------------------------------------------------------------
// Scratch (static device globals; fp16 single-precision path, fp32 accum)
// ---------------------------------------------------------------------------
__device__ __half g_x1[BSS * DD];                 // LN1 out
__device__ __half g_wqkv[QKVN * DD];              // [N=3072,K=1024]
__device__ float  g_bqkv[QKVN];
__device__ __half g_qkv[(size_t)BSS * QKVN];      // q(0.125*log2e-folded)|k|v
__device__ __half g_z[BSS * DD];                  // attention out
__device__ __half g_wo[DD * DD];                  // [N=1024,K=1024]
__device__ float  g_rmid[BSS * DD];
__device__ __half g_x2[BSS * DD];                 // LN2 out
__device__ __half g_win[DMM * DD];                // [N=4096,K=1024]
__device__ __half g_h[(size_t)BSS * DMM];         // MLP hidden
__device__ __half g_wout[DD * DMM];               // [N=1024,K=4096]

// ---------------------------------------------------------------------------
// PTX helpers (baseline ISA: ldmatrix / mma.sync / cp.async / mbarrier)
// ---------------------------------------------------------------------------
__device__ __forceinline__ uint32_t smem_u32(const void* p) {
    uint32_t a;
    asm("{ .reg .u64 t; cvta.to.shared.u64 t, %1; cvt.u32.u64 %0, t; }" : "=r"(a) : "l"(p));
    return a;
}
__device__ __forceinline__ void ldsm4(uint32_t& r0, uint32_t& r1, uint32_t& r2,
                                      uint32_t& r3, uint32_t a) {
    asm volatile("ldmatrix.sync.aligned.m8n8.x4.shared.b16 {%0,%1,%2,%3}, [%4];"
                 : "=r"(r0), "=r"(r1), "=r"(r2), "=r"(r3) : "r"(a));
}
__device__ __forceinline__ void ldsm4t(uint32_t& r0, uint32_t& r1, uint32_t& r2,
                                       uint32_t& r3, uint32_t a) {
    asm volatile("ldmatrix.sync.aligned.m8n8.x4.trans.shared.b16 {%0,%1,%2,%3}, [%4];"
                 : "=r"(r0), "=r"(r1), "=r"(r2), "=r"(r3) : "r"(a));
}
__device__ __forceinline__ void mma16816(float* c, const uint32_t* a, const uint32_t* b) {
    asm volatile(
        "mma.sync.aligned.m16n8k16.row.col.f32.f16.f16.f32 "
        "{%0,%1,%2,%3},{%4,%5,%6,%7},{%8,%9},{%0,%1,%2,%3};"
        : "+f"(c[0]), "+f"(c[1]), "+f"(c[2]), "+f"(c[3])
        : "r"(a[0]), "r"(a[1]), "r"(a[2]), "r"(a[3]), "r"(b[0]), "r"(b[1]));
}
__device__ __forceinline__ void mma2(float* c, const uint32_t* a, uint32_t b0, uint32_t b1) {
    asm volatile(
        "mma.sync.aligned.m16n8k16.row.col.f32.f16.f16.f32 "
        "{%0,%1,%2,%3},{%4,%5,%6,%7},{%8,%9},{%0,%1,%2,%3};"
        : "+f"(c[0]), "+f"(c[1]), "+f"(c[2]), "+f"(c[3])
        : "r"(a[0]), "r"(a[1]), "r"(a[2]), "r"(a[3]), "r"(b0), "r"(b1));
}
__device__ __forceinline__ void cp16(uint32_t d, const void* s) {
    asm volatile("cp.async.cg.shared.global [%0], [%1], 16;" :: "r"(d), "l"(s) : "memory");
}
#define CP_COMMIT() asm volatile("cp.async.commit_group;" ::: "memory")

__device__ __forceinline__ void mbar_init(uint32_t a, uint32_t cnt) {
    asm volatile("mbarrier.init.shared.b64 [%0], %1;" :: "r"(a), "r"(cnt) : "memory");
}
__device__ __forceinline__ void mbar_arrive(uint32_t a) {
    asm volatile("mbarrier.arrive.shared.b64 _, [%0];" :: "r"(a) : "memory");
}
__device__ __forceinline__ void cp_mbar_arrive(uint32_t a) {
    asm volatile("cp.async.mbarrier.arrive.noinc.shared.b64 [%0];" :: "r"(a) : "memory");
}
__device__ __forceinline__ void mbar_wait(uint32_t a, uint32_t parity) {
    asm volatile(
        "{\n\t.reg .pred P;\n\t"
        "WL_%=:\n\t"
        "mbarrier.try_wait.parity.acquire.cta.shared::cta.b64 P, [%0], %1, 0x989680;\n\t"
        "@P bra.uni WD_%=;\n\t"
        "bra.uni WL_%=;\n\t"
        "WD_%=:\n\t}"
        :: "r"(a), "r"(parity) : "memory");
}

__device__ __forceinline__ uint32_t f2h2(float a, float b) {
    __half2 h = __floats2half2_rn(a, b);
    return *(uint32_t*)&h;
}

// ---------------------------------------------------------------------------
// Block reduction
// ---------------------------------------------------------------------------
__device__ __forceinline__ float block_sum(float v, float* red) {
    __syncthreads();
    int lane = threadIdx.x & 31, wid = threadIdx.x >> 5;
    #pragma unroll
    for (int o = 16; o > 0; o >>= 1) v += __shfl_xor_sync(0xffffffffu, v, o);
    if (lane == 0) red[wid] = v;
    __syncthreads();
    float t = (threadIdx.x < (blockDim.x >> 5)) ? red[threadIdx.x] : 0.f;
    if (wid == 0) {
        #pragma unroll
        for (int o = 16; o > 0; o >>= 1) t += __shfl_xor_sync(0xffffffffu, t, o);
        if (lane == 0) red[0] = t;
    }
    __syncthreads();
    return red[0];
}

// ---------------------------------------------------------------------------
// LN row body (register-resident, 256 threads x float4)
// ---------------------------------------------------------------------------
__device__ __forceinline__ void ln_body(const float* __restrict__ x,
                                        const float* __restrict__ w,
                                        const float* __restrict__ b,
                                        __half* __restrict__ o, int r, float* red) {
    int tid = threadIdx.x;
    float4 v = ((const float4*)(x + (size_t)r * DD))[tid];
    float s = block_sum(v.x + v.y + v.z + v.w, red);
    float mean = s * (1.f / DD);
    float dx = v.x - mean, dy = v.y - mean, dz = v.z - mean, dw = v.w - mean;
    float q = block_sum(dx * dx + dy * dy + dz * dz + dw * dw, red);
    float inv = rsqrtf(q * (1.f / DD) + LN_EPS);
    float4 w4 = ((const float4*)w)[tid];
    float4 b4 = ((const float4*)b)[tid];
    __half2 h0 = __floats2half2_rn(dx * inv * w4.x + b4.x, dy * inv * w4.y + b4.y);
    __half2 h1 = __floats2half2_rn(dz * inv * w4.z + b4.z, dw * inv * w4.w + b4.w);
    uint2 pk; pk.x = *(uint32_t*)&h0; pk.y = *(uint32_t*)&h1;
    ((uint2*)(o + (size_t)r * DD))[tid] = pk;
}

// conv_wT body: W fp32 [K,N] tile -> B fp16 [N,K]
__device__ __forceinline__ void wT_body(const float* __restrict__ W,
                                        __half* __restrict__ B, int K, int N,
                                        int n0, int k0, float* t /*32x33*/) {
    int tid = threadIdx.x;
    int tx = tid & 31, ty = tid >> 5;
    #pragma unroll
    for (int i = 0; i < 4; i++)
        t[(ty + i * 8) * 33 + tx] = W[(size_t)(k0 + ty + i * 8) * N + n0 + tx];
    __syncthreads();
    #pragma unroll
    for (int i = 0; i < 4; i++) {
        int n = n0 + ty + i * 8, k = k0 + tx;
        B[(size_t)n * K + k] = __float2half_rn(t[tx * 33 + ty + i * 8]);
    }
}

// ---------------------------------------------------------------------------
// prep_kernel: ALL weight conversions + bias pack + LN1 in ONE launch.
// ---------------------------------------------------------------------------
#define PREP_BLOCKS 13828

__global__ __launch_bounds__(256)
void prep_kernel(const float* __restrict__ WQ, const float* __restrict__ WK,
                 const float* __restrict__ WV, const float* __restrict__ bQ,
                 const float* __restrict__ bK, const float* __restrict__ bV,
                 const float* __restrict__ WO, const float* __restrict__ Win,
                 const float* __restrict__ Wout, const float* __restrict__ resid,
                 const float* __restrict__ ln1w, const float* __restrict__ ln1b) {
    __shared__ float smf[32 * 65];
    int bid = blockIdx.x;
    int tid = threadIdx.x;

    if (bid < 4096) {
        int n0 = (bid & 127) * 32, k0 = (bid >> 7) * 32;
        wT_body(Win, g_win, DD, DMM, n0, k0, smf);
        return;
    }
    bid -= 4096;
    if (bid < 4096) {
        int n0 = (bid & 31) * 32, k0 = (bid >> 5) * 32;
        wT_body(Wout, g_wout, DMM, DD, n0, k0, smf);
        return;
    }
    bid -= 4096;
    if (bid < 4096) {
        ln_body(resid, ln1w, ln1b, g_x1, bid, smf);
        return;
    }
    bid -= 4096;
    if (bid < 1024) {
        int n0 = (bid & 31) * 32, k0 = (bid >> 5) * 32;
        wT_body(WO, g_wo, DD, DD, n0, k0, smf);
        return;
    }
    bid -= 1024;
    if (bid < 512) {
        int k0 = (bid & 31) * 32, h = bid >> 5;
        const float* Ws[3] = {WQ, WK, WV};
        for (int s = 0; s < 3; s++) {
            const float* src = Ws[s] + (size_t)h * DD * DHH + (size_t)k0 * DHH;
            #pragma unroll
            for (int it = 0; it < 8; it++) {
                int idx = tid + it * 256;
                smf[(idx >> 6) * 65 + (idx & 63)] = src[idx];
            }
            __syncthreads();
            #pragma unroll
            for (int it = 0; it < 8; it++) {
                int idx = tid + it * 256;
                int dh = idx >> 5, kk = idx & 31;
                size_t n = (size_t)s * DD + h * 64 + dh;
                g_wqkv[n * DD + k0 + kk] = __float2half_rn(smf[kk * 65 + dh]);
            }
            __syncthreads();
        }
        return;
    }
    bid -= 512;
    {
        int i = bid * 256 + tid;
        g_bqkv[i]          = bQ[i];
        g_bqkv[DD + i]     = bK[i];
        g_bqkv[2 * DD + i] = bV[i];
    }
}

__device__ __forceinline__ float gelu_tanh(float x) {
    float x3 = x * x * x;
    return 0.5f * x * (1.f + tanhf(0.7978845608028654f * (x + 0.044715f * x3)));
}

// ---------------------------------------------------------------------------
// LN2 (standalone; depends on rmid)
// ---------------------------------------------------------------------------
__global__ __launch_bounds__(256)
void ln_kernel(const float* __restrict__ x, const float* __restrict__ w,
               const float* __restrict__ b, __half* __restrict__ o) {
    __shared__ float red[32];
    ln_body(x, w, b, o, blockIdx.x, red);
}

// ---------------------------------------------------------------------------
// HMMA fp16 GEMM: C = A @ B^T + bias ; fp32 accumulate.
// 128x128 CTA tile, 256 threads, 8 warps (2x4), warp tile 64x32, K-tile 64.
// DE-PHASED pipeline: 3-stage ring with per-stage full/empty mbarriers
// (cp.async.mbarrier.arrive.noinc) instead of per-tile __syncthreads -> warps
// drift, smoothing ldsm/MMA bursts (R13 profile: issue 16.6% with all pipes
// underutilized = phase-convergence stall).
// full[s]: 256 noinc arrivals (every thread's cp.async). empty[s]: 256 arrivals.
// Consumer tile t: wait full[t%3] parity (t/3)&1.
// Producer tile p>=3: wait empty[p%3] parity (p/3-1)&1. Tiles 0-2 unconditional.
// ---------------------------------------------------------------------------
#define GOPD 18432                   // 128 rows * 144 B
#define GBUF (2 * GOPD)              // A | B per stage: 36864
#define GEMM_SMEM (3 * GBUF + 64)    // ring + mbarriers: 110656

__device__ __forceinline__ void gemm_load_nb(uint32_t dst, const char* const* src,
                                             size_t rowB, int k0b, int tid) {
    #pragma unroll
    for (int it = 0; it < 8; it++) {
        int c = tid + it * 256;
        int o = c >> 10, r = c & 1023, row = r >> 3, kc = r & 7;
        cp16(dst + o * GOPD + row * 144 + kc * 16,
             src[o] + (size_t)row * rowB + k0b + kc * 16);
    }
}

template <int EPI>
__global__ __launch_bounds__(256, 2)
void gemm_hmma(const __half* __restrict__ A, const __half* __restrict__ B,
               const float* __restrict__ bias, const float* __restrict__ R,
               float* __restrict__ Cf, __half* __restrict__ Ch,
               int M, int N, int K) {
    extern __shared__ char sm[];
    const uint32_t sb = smem_u32(sm);
    const uint32_t mb = sb + 3 * GBUF;          // full[0..2] @ +0/8/16, empty @ +24/32/40
    const int tid = threadIdx.x;
    const int wid = tid >> 5, lid = tid & 31;
    const int warp_m = wid >> 2, warp_n = wid & 3;

    if (tid == 0) {
        #pragma unroll
        for (int s = 0; s < 3; s++) {
            mbar_init(mb + s * 8, 256);         // full[s]
            mbar_init(mb + 24 + s * 8, 256);    // empty[s]
        }
    }
    __syncthreads();

    const char* src[2];
    src[0] = (const char*)(A + (size_t)blockIdx.y * 128 * K);
    src[1] = (const char*)(B + (size_t)blockIdx.x * 128 * K);
    const size_t rowB = (size_t)K * 2;

    const int g = lid >> 3, li = lid & 7;
    const int a_row = (g & 1) * 8 + li, a_kb = (g >> 1) * 16;
    const int b_row = (g >> 1) * 8 + li, b_kb = (g & 1) * 16;

    float acc[4][4][4];
    #pragma unroll
    for (int mt = 0; mt < 4; mt++)
        #pragma unroll
        for (int nt = 0; nt < 4; nt++)
            #pragma unroll
            for (int e = 0; e < 4; e++) acc[mt][nt][e] = 0.f;

    const int T = K >> 6;   // K-tiles of 64 (>= 16 always)

    // prologue: produce tiles 0,1,2 (first use of each slot: no empty wait)
    #pragma unroll
    for (int p = 0; p < 3; p++) {
        gemm_load_nb(sb + p * GBUF, src, rowB, p * 128, tid);
        cp_mbar_arrive(mb + p * 8);
    }

    for (int t = 0; t < T; t++) {
        const int s = t % 3;
        mbar_wait(mb + s * 8, (uint32_t)((t / 3) & 1));   // full[s]

        uint32_t buf = sb + s * GBUF;
        uint32_t aP = buf + (warp_m * 64 + a_row) * 144 + a_kb;
        uint32_t bP = buf + GOPD + (warp_n * 32 + b_row) * 144 + b_kb;

        #pragma unroll
        for (int kk = 0; kk < 4; kk++) {
            uint32_t bh[4][2];
            ldsm4(bh[0][0], bh[0][1], bh[1][0], bh[1][1], bP + kk * 32);
            ldsm4(bh[2][0], bh[2][1], bh[3][0], bh[3][1], bP + 16 * 144 + kk * 32);
            #pragma unroll
            for (int mt = 0; mt < 4; mt++) {
                uint32_t ah[4];
                ldsm4(ah[0], ah[1], ah[2], ah[3], aP + mt * 16 * 144 + kk * 32);
                #pragma unroll
                for (int nt = 0; nt < 4; nt++)
                    mma16816(acc[mt][nt], ah, bh[nt]);
            }
        }

        mbar_arrive(mb + 24 + s * 8);                     // empty[s]

        // produce tile t+3 into slot s (needs this tile consumed by ALL warps)
        if (t + 3 < T) {
            mbar_wait(mb + 24 + s * 8, (uint32_t)((t / 3) & 1));  // empty[s] use t/3
            gemm_load_nb(buf, src, rowB, (t + 3) * 128, tid);
            cp_mbar_arrive(mb + s * 8);
        }
    }

    const int group = lid >> 2, t4 = lid & 3;
    const size_t rbase = (size_t)blockIdx.y * 128 + warp_m * 64;
    const int cbase = blockIdx.x * 128 + warp_n * 32;
    #pragma unroll
    for (int mt = 0; mt < 4; mt++) {
        size_t r0 = rbase + mt * 16 + group;
        size_t r1 = r0 + 8;
        #pragma unroll
        for (int nt = 0; nt < 4; nt++) {
            int col = cbase + nt * 8 + t4 * 2;
            float* c = acc[mt][nt];
            float b0 = bias[col], b1 = bias[col + 1];
            float x0 = c[0] + b0, x1 = c[1] + b1;
            float x2 = c[2] + b0, x3 = c[3] + b1;
            if (EPI == 1 || EPI == 3) {
                if (EPI == 1) {
                    x0 = gelu_tanh(x0); x1 = gelu_tanh(x1);
                    x2 = gelu_tanh(x2); x3 = gelu_tanh(x3);
                } else {
                    // fold 1/sqrt(DH) AND log2(e) into Q -> scores are base-2 logits
                    float qsc = (blockIdx.x < 8) ? 0.125f * LOG2E : 1.0f;
                    x0 *= qsc; x1 *= qsc; x2 *= qsc; x3 *= qsc;
                }
                *(__half2*)(Ch + r0 * N + col) = __floats2half2_rn(x0, x1);
                *(__half2*)(Ch + r1 * N + col) = __floats2half2_rn(x2, x3);
            } else {
                float2 ra = *(const float2*)(R + r0 * N + col);
                float2 rb = *(const float2*)(R + r1 * N + col);
                x0 += ra.x; x1 += ra.y; x2 += rb.x; x3 += rb.y;
                float2 va; va.x = x0; va.y = x1;
                float2 vb; vb.x = x2; vb.y = x3;
                *(float2*)(Cf + r0 * N + col) = va;
                *(float2*)(Cf + r1 * N + col) = vb;
            }
        }
    }
}

// ---------------------------------------------------------------------------
// flash2: tensor-core causal flash attention (unchanged from R13 winner).
// ---------------------------------------------------------------------------
#define FPB 144
#define FL_KV 18432
#define FL_TILE 9216
#define FL_BUF 18432
#define FLASH2_SMEM (FL_KV + 3 * FL_BUF)   // 73728

__device__ __forceinline__ void fl_load_kv(uint32_t sb, const __half* base,
                                           int kt, int bi, int tid) {
    uint32_t dst0 = sb + FL_KV + bi * FL_BUF;
    #pragma unroll
    for (int it = 0; it < 4; it++) {
        int idx = tid + it * 256;
        int reg = idx >> 9;
        int r = idx & 511;
        int row = r >> 3, c = r & 7;
        const __half* s = base + (size_t)(kt * 64 + row) * QKVN + DD + reg * DD + c * 8;
        cp16(dst0 + reg * FL_TILE + row * FPB + c * 16, s);
    }
    CP_COMMIT();
}

__global__ __launch_bounds__(256, 2)
void flash2(const __half* __restrict__ qkv, __half* __restrict__ z) {
    extern __shared__ char sm[];
    const uint32_t sb = smem_u32(sm);
    const int tid = threadIdx.x, wid = tid >> 5, lid = tid & 31;
    const int qt = (int)gridDim.x - 1 - (int)blockIdx.x;
    const int h = blockIdx.y, b = blockIdx.z;

    const __half* base = qkv + (size_t)b * SS * QKVN + h * 64;
    const int nkt = 2 * qt + 2;

    #pragma unroll
    for (int it = 0; it < 4; it++) {
        int idx = tid + it * 256;
        int row = idx >> 3, c = idx & 7;
        cp16(sb + row * FPB + c * 16, base + (size_t)(qt * 128 + row) * QKVN + c * 8);
    }
    CP_COMMIT();
    fl_load_kv(sb, base, 0, 0, tid);
    fl_load_kv(sb, base, 1, 1, tid);

    asm volatile("cp.async.wait_group 2;" ::: "memory");
    __syncthreads();

    const int g2 = lid >> 3, li = lid & 7;
    const int a_row = (g2 & 1) * 8 + li, a_kb = (g2 >> 1) * 16;
    const uint32_t qa = sb + (wid * 16 + a_row) * FPB + a_kb;
    uint32_t qh[4][4];
    #pragma unroll
    for (int kc = 0; kc < 4; kc++)
        ldsm4(qh[kc][0], qh[kc][1], qh[kc][2], qh[kc][3], qa + kc * 32);

    float o[8][4];
    #pragma unroll
    for (int nt = 0; nt < 8; nt++)
        #pragma unroll
        for (int e = 0; e < 4; e++) o[nt][e] = 0.f;
    float m0 = -1e30f, m1 = -1e30f, l0 = 0.f, l1 = 0.f;

    const int gq = lid >> 2, t4 = lid & 3;
    const int row0g = qt * 128 + wid * 16 + gq;
    const int row1g = row0g + 8;

    const uint32_t kb_off = (uint32_t)(((g2 >> 1) * 8 + li) * FPB + (g2 & 1) * 16);
    const uint32_t v_off  = (uint32_t)(((g2 & 1) * 8 + li) * FPB + (g2 >> 1) * 16);

    int bufsel = 0;
    for (int kt = 0; kt < nkt; kt++) {
        if (kt + 1 < nkt) { asm volatile("cp.async.wait_group 1;" ::: "memory"); }
        else              { asm volatile("cp.async.wait_group 0;" ::: "memory"); }
        __syncthreads();

        if (kt + 2 < nkt) {
            int nb = bufsel + 2; if (nb >= 3) nb -= 3;
            fl_load_kv(sb, base, kt + 2, nb, tid);
        }

        const uint32_t buf = sb + FL_KV + bufsel * FL_BUF;

        float s[8][4];
        #pragma unroll
        for (int nt = 0; nt < 8; nt++)
            #pragma unroll
            for (int e = 0; e < 4; e++) s[nt][e] = 0.f;

        #pragma unroll
        for (int kc = 0; kc < 4; kc++) {
            #pragma unroll
            for (int ntp = 0; ntp < 4; ntp++) {
                uint32_t ka = buf + kb_off + ntp * 16 * FPB + kc * 32;
                uint32_t h0, h1, h2, h3;
                ldsm4(h0, h1, h2, h3, ka);
                mma2(s[2 * ntp],     qh[kc], h0, h1);
                mma2(s[2 * ntp + 1], qh[kc], h2, h3);
            }
        }

        if (kt >= 2 * qt) {
            int colb = kt * 64 + 2 * t4;
            #pragma unroll
            for (int nt = 0; nt < 8; nt++) {
                int c0 = colb + nt * 8, c1 = c0 + 1;
                if (c0 > row0g) s[nt][0] = -1e30f;
                if (c1 > row0g) s[nt][1] = -1e30f;
                if (c0 > row1g) s[nt][2] = -1e30f;
                if (c1 > row1g) s[nt][3] = -1e30f;
            }
        }

        float tm0 = -1e30f, tm1 = -1e30f;
        #pragma unroll
        for (int nt = 0; nt < 8; nt++) {
            tm0 = fmaxf(tm0, fmaxf(s[nt][0], s[nt][1]));
            tm1 = fmaxf(tm1, fmaxf(s[nt][2], s[nt][3]));
        }
        tm0 = fmaxf(tm0, __shfl_xor_sync(0xffffffffu, tm0, 1));
        tm0 = fmaxf(tm0, __shfl_xor_sync(0xffffffffu, tm0, 2));
        tm1 = fmaxf(tm1, __shfl_xor_sync(0xffffffffu, tm1, 1));
        tm1 = fmaxf(tm1, __shfl_xor_sync(0xffffffffu, tm1, 2));
        float mn0 = fmaxf(m0, tm0), mn1 = fmaxf(m1, tm1);
        float al0 = exp2f(m0 - mn0), al1 = exp2f(m1 - mn1);
        m0 = mn0; m1 = mn1;

        float rs0 = 0.f, rs1 = 0.f;
        #pragma unroll
        for (int nt = 0; nt < 8; nt++) {
            s[nt][0] = exp2f(s[nt][0] - mn0); rs0 += s[nt][0];
            s[nt][1] = exp2f(s[nt][1] - mn0); rs0 += s[nt][1];
            s[nt][2] = exp2f(s[nt][2] - mn1); rs1 += s[nt][2];
            s[nt][3] = exp2f(s[nt][3] - mn1); rs1 += s[nt][3];
        }
        rs0 += __shfl_xor_sync(0xffffffffu, rs0, 1);
        rs0 += __shfl_xor_sync(0xffffffffu, rs0, 2);
        rs1 += __shfl_xor_sync(0xffffffffu, rs1, 1);
        rs1 += __shfl_xor_sync(0xffffffffu, rs1, 2);
        l0 = l0 * al0 + rs0;
        l1 = l1 * al1 + rs1;
        #pragma unroll
        for (int nt = 0; nt < 8; nt++) {
            o[nt][0] *= al0; o[nt][1] *= al0;
            o[nt][2] *= al1; o[nt][3] *= al1;
        }

        uint32_t pa[4][4];
        #pragma unroll
        for (int kc = 0; kc < 4; kc++) {
            pa[kc][0] = f2h2(s[2 * kc][0],     s[2 * kc][1]);
            pa[kc][1] = f2h2(s[2 * kc][2],     s[2 * kc][3]);
            pa[kc][2] = f2h2(s[2 * kc + 1][0], s[2 * kc + 1][1]);
            pa[kc][3] = f2h2(s[2 * kc + 1][2], s[2 * kc + 1][3]);
        }

        #pragma unroll
        for (int kc = 0; kc < 4; kc++) {
            #pragma unroll
            for (int ntp = 0; ntp < 4; ntp++) {
                uint32_t va = buf + FL_TILE + kc * 16 * FPB + ntp * 32 + v_off;
                uint32_t h0, h1, h2, h3;
                ldsm4t(h0, h1, h2, h3, va);
                mma2(o[2 * ntp],     pa[kc], h0, h1);
                mma2(o[2 * ntp + 1], pa[kc], h2, h3);
            }
        }
        if (++bufsel == 3) bufsel = 0;
    }

    float iv0 = 1.f / l0, iv1 = 1.f / l1;
    size_t r0 = (size_t)b * SS + qt * 128 + wid * 16 + gq;
    size_t r1 = r0 + 8;
    #pragma unroll
    for (int nt = 0; nt < 8; nt++) {
        int col = h * 64 + nt * 8 + 2 * t4;
        *(__half2*)(z + r0 * DD + col) = __floats2half2_rn(o[nt][0] * iv0, o[nt][1] * iv0);
        *(__half2*)(z + r1 * DD + col) = __floats2half2_rn(o[nt][2] * iv1, o[nt][3] * iv1);
    }
}

// ---------------------------------------------------------------------------
// Launch
// ---------------------------------------------------------------------------
extern "C" void kernel_launch(void* const* d_in, const int* in_sizes, int n_in,
                              void* d_out, int out_size) {
    (void)in_sizes; (void)n_in; (void)out_size;
    const float* resid_pre = (const float*)d_in[0];
    const float* ln1_w = (const float*)d_in[1];
    const float* ln1_b = (const float*)d_in[2];
    const float* W_Q   = (const float*)d_in[3];
    const float* W_K   = (const float*)d_in[4];
    const float* W_V   = (const float*)d_in[5];
    const float* W_O   = (const float*)d_in[6];
    const float* b_Q   = (const float*)d_in[7];
    const float* b_K   = (const float*)d_in[8];
    const float* b_V   = (const float*)d_in[9];
    const float* b_O   = (const float*)d_in[10];
    const float* ln2_w = (const float*)d_in[11];
    const float* ln2_b = (const float*)d_in[12];
    const float* W_in  = (const float*)d_in[13];
    const float* b_in  = (const float*)d_in[14];
    const float* W_out = (const float*)d_in[15];
    const float* b_out = (const float*)d_in[16];
    float* out = (float*)d_out;

    __half *p_x1, *p_wqkv, *p_qkv, *p_z, *p_wo, *p_x2, *p_win, *p_h, *p_wout;
    float *p_bqkv, *p_rmid;
    cudaGetSymbolAddress((void**)&p_x1, g_x1);
    cudaGetSymbolAddress((void**)&p_wqkv, g_wqkv);
    cudaGetSymbolAddress((void**)&p_bqkv, g_bqkv);
    cudaGetSymbolAddress((void**)&p_qkv, g_qkv);
    cudaGetSymbolAddress((void**)&p_z, g_z);
    cudaGetSymbolAddress((void**)&p_wo, g_wo);
    cudaGetSymbolAddress((void**)&p_rmid, g_rmid);
    cudaGetSymbolAddress((void**)&p_x2, g_x2);
    cudaGetSymbolAddress((void**)&p_win, g_win);
    cudaGetSymbolAddress((void**)&p_h, g_h);
    cudaGetSymbolAddress((void**)&p_wout, g_wout);

    cudaFuncSetAttribute(flash2, cudaFuncAttributeMaxDynamicSharedMemorySize, FLASH2_SMEM);
    cudaFuncSetAttribute(gemm_hmma<1>, cudaFuncAttributeMaxDynamicSharedMemorySize, GEMM_SMEM);
    cudaFuncSetAttribute(gemm_hmma<2>, cudaFuncAttributeMaxDynamicSharedMemorySize, GEMM_SMEM);
    cudaFuncSetAttribute(gemm_hmma<3>, cudaFuncAttributeMaxDynamicSharedMemorySize, GEMM_SMEM);

    // ALL prep (weight conversions + bias pack + LN1) in one launch
    prep_kernel<<<PREP_BLOCKS, 256>>>(W_Q, W_K, W_V, b_Q, b_K, b_V,
                                      W_O, W_in, W_out,
                                      resid_pre, ln1_w, ln1_b);

    // QKV projection -> fp16 (Q scaled by 0.125*log2e)
    gemm_hmma<3><<<dim3(QKVN / 128, BSS / 128), 256, GEMM_SMEM>>>(
        p_x1, p_wqkv, p_bqkv, nullptr, nullptr, p_qkv, BSS, QKVN, DD);

    // flash attention (tensor cores, base-2 softmax) -> z
    flash2<<<dim3(SS / 128, HH, BB), 256, FLASH2_SMEM>>>(p_qkv, p_z);

    // O projection + residual -> rmid fp32
    gemm_hmma<2><<<dim3(DD / 128, BSS / 128), 256, GEMM_SMEM>>>(
        p_z, p_wo, b_O, resid_pre, p_rmid, nullptr, BSS, DD, DD);

    // LN2
    ln_kernel<<<BSS, 256>>>(p_rmid, ln2_w, ln2_b, p_x2);

    // MLP in + gelu -> h fp16
    gemm_hmma<1><<<dim3(DMM / 128, BSS / 128), 256, GEMM_SMEM>>>(
        p_x2, p_win, b_in, nullptr, nullptr, p_h, BSS, DMM, DD);

    // MLP out + residual -> out fp32
    gemm_hmma<2><<<dim3(DD / 128, BSS / 128), 256, GEMM_SMEM>>>(
        p_h, p_wout, b_out, p_rmid, out, nullptr, BSS, DD, DMM);
}

// round 15
// speedup vs baseline: 1.1980x; 1.0362x over previous
#include <cuda_runtime.h>
#include <cuda_fp16.h>
#include <cstdint>
#include <cstddef>

// ---------------------------------------------------------------------------
// Problem constants
// ---------------------------------------------------------------------------
#define BB   2
#define SS   2048
#define DD   1024
#define HH   16
#define DHH  64
#define DMM  4096
#define BSS  (BB * SS)          // 4096 rows
#define QKVN (3 * DD)           // 3072
#define LN_EPS 1e-5f
#define LOG2E 1.4426950408889634f

// ---------------------------------------------------------------------------
// Scratch (static device globals; fp16 single-precision path, fp32 accum)
// ---------------------------------------------------------------------------
__device__ __half g_x1[BSS * DD];                 // LN1 out
__device__ __half g_wqkv[QKVN * DD];              // [N=3072,K=1024]
__device__ float  g_bqkv[QKVN];
__device__ __half g_qkv[(size_t)BSS * QKVN];      // q(0.125*log2e-folded)|k|v
__device__ __half g_z[BSS * DD];                  // attention out
__device__ __half g_wo[DD * DD];                  // [N=1024,K=1024]
__device__ float  g_rmid[BSS * DD];
__device__ __half g_x2[BSS * DD];                 // LN2 out
__device__ __half g_win[DMM * DD];                // [N=4096,K=1024]
__device__ __half g_h[(size_t)BSS * DMM];         // MLP hidden
__device__ __half g_wout[DD * DMM];               // [N=1024,K=4096]

// ---------------------------------------------------------------------------
// PTX helpers (baseline ISA: ldmatrix / mma.sync / cp.async / mbarrier)
// ---------------------------------------------------------------------------
__device__ __forceinline__ uint32_t smem_u32(const void* p) {
    uint32_t a;
    asm("{ .reg .u64 t; cvta.to.shared.u64 t, %1; cvt.u32.u64 %0, t; }" : "=r"(a) : "l"(p));
    return a;
}
__device__ __forceinline__ void ldsm4(uint32_t& r0, uint32_t& r1, uint32_t& r2,
                                      uint32_t& r3, uint32_t a) {
    asm volatile("ldmatrix.sync.aligned.m8n8.x4.shared.b16 {%0,%1,%2,%3}, [%4];"
                 : "=r"(r0), "=r"(r1), "=r"(r2), "=r"(r3) : "r"(a));
}
__device__ __forceinline__ void ldsm4t(uint32_t& r0, uint32_t& r1, uint32_t& r2,
                                       uint32_t& r3, uint32_t a) {
    asm volatile("ldmatrix.sync.aligned.m8n8.x4.trans.shared.b16 {%0,%1,%2,%3}, [%4];"
                 : "=r"(r0), "=r"(r1), "=r"(r2), "=r"(r3) : "r"(a));
}
__device__ __forceinline__ void mma16816(float* c, const uint32_t* a, const uint32_t* b) {
    asm volatile(
        "mma.sync.aligned.m16n8k16.row.col.f32.f16.f16.f32 "
        "{%0,%1,%2,%3},{%4,%5,%6,%7},{%8,%9},{%0,%1,%2,%3};"
        : "+f"(c[0]), "+f"(c[1]), "+f"(c[2]), "+f"(c[3])
        : "r"(a[0]), "r"(a[1]), "r"(a[2]), "r"(a[3]), "r"(b[0]), "r"(b[1]));
}
__device__ __forceinline__ void mma2(float* c, const uint32_t* a, uint32_t b0, uint32_t b1) {
    asm volatile(
        "mma.sync.aligned.m16n8k16.row.col.f32.f16.f16.f32 "
        "{%0,%1,%2,%3},{%4,%5,%6,%7},{%8,%9},{%0,%1,%2,%3};"
        : "+f"(c[0]), "+f"(c[1]), "+f"(c[2]), "+f"(c[3])
        : "r"(a[0]), "r"(a[1]), "r"(a[2]), "r"(a[3]), "r"(b0), "r"(b1));
}
__device__ __forceinline__ void cp16(uint32_t d, const void* s) {
    asm volatile("cp.async.cg.shared.global [%0], [%1], 16;" :: "r"(d), "l"(s) : "memory");
}
#define CP_COMMIT() asm volatile("cp.async.commit_group;" ::: "memory")

__device__ __forceinline__ void mbar_init(uint32_t a, uint32_t cnt) {
    asm volatile("mbarrier.init.shared.b64 [%0], %1;" :: "r"(a), "r"(cnt) : "memory");
}
__device__ __forceinline__ void mbar_arrive(uint32_t a) {
    asm volatile("mbarrier.arrive.shared.b64 _, [%0];" :: "r"(a) : "memory");
}
__device__ __forceinline__ void cp_mbar_arrive(uint32_t a) {
    asm volatile("cp.async.mbarrier.arrive.noinc.shared.b64 [%0];" :: "r"(a) : "memory");
}
__device__ __forceinline__ void mbar_wait(uint32_t a, uint32_t parity) {
    asm volatile(
        "{\n\t.reg .pred P;\n\t"
        "WL_%=:\n\t"
        "mbarrier.try_wait.parity.acquire.cta.shared::cta.b64 P, [%0], %1, 0x989680;\n\t"
        "@P bra.uni WD_%=;\n\t"
        "bra.uni WL_%=;\n\t"
        "WD_%=:\n\t}"
        :: "r"(a), "r"(parity) : "memory");
}

__device__ __forceinline__ uint32_t f2h2(float a, float b) {
    __half2 h = __floats2half2_rn(a, b);
    return *(uint32_t*)&h;
}

// ---------------------------------------------------------------------------
// Block reduction
// ---------------------------------------------------------------------------
__device__ __forceinline__ float block_sum(float v, float* red) {
    __syncthreads();
    int lane = threadIdx.x & 31, wid = threadIdx.x >> 5;
    #pragma unroll
    for (int o = 16; o > 0; o >>= 1) v += __shfl_xor_sync(0xffffffffu, v, o);
    if (lane == 0) red[wid] = v;
    __syncthreads();
    float t = (threadIdx.x < (blockDim.x >> 5)) ? red[threadIdx.x] : 0.f;
    if (wid == 0) {
        #pragma unroll
        for (int o = 16; o > 0; o >>= 1) t += __shfl_xor_sync(0xffffffffu, t, o);
        if (lane == 0) red[0] = t;
    }
    __syncthreads();
    return red[0];
}

// ---------------------------------------------------------------------------
// LN row body (register-resident, 256 threads x float4)
// ---------------------------------------------------------------------------
__device__ __forceinline__ void ln_body(const float* __restrict__ x,
                                        const float* __restrict__ w,
                                        const float* __restrict__ b,
                                        __half* __restrict__ o, int r, float* red) {
    int tid = threadIdx.x;
    float4 v = ((const float4*)(x + (size_t)r * DD))[tid];
    float s = block_sum(v.x + v.y + v.z + v.w, red);
    float mean = s * (1.f / DD);
    float dx = v.x - mean, dy = v.y - mean, dz = v.z - mean, dw = v.w - mean;
    float q = block_sum(dx * dx + dy * dy + dz * dz + dw * dw, red);
    float inv = rsqrtf(q * (1.f / DD) + LN_EPS);
    float4 w4 = ((const float4*)w)[tid];
    float4 b4 = ((const float4*)b)[tid];
    __half2 h0 = __floats2half2_rn(dx * inv * w4.x + b4.x, dy * inv * w4.y + b4.y);
    __half2 h1 = __floats2half2_rn(dz * inv * w4.z + b4.z, dw * inv * w4.w + b4.w);
    uint2 pk; pk.x = *(uint32_t*)&h0; pk.y = *(uint32_t*)&h1;
    ((uint2*)(o + (size_t)r * DD))[tid] = pk;
}

// conv_wT body: W fp32 [K,N] tile -> B fp16 [N,K]
__device__ __forceinline__ void wT_body(const float* __restrict__ W,
                                        __half* __restrict__ B, int K, int N,
                                        int n0, int k0, float* t /*32x33*/) {
    int tid = threadIdx.x;
    int tx = tid & 31, ty = tid >> 5;
    #pragma unroll
    for (int i = 0; i < 4; i++)
        t[(ty + i * 8) * 33 + tx] = W[(size_t)(k0 + ty + i * 8) * N + n0 + tx];
    __syncthreads();
    #pragma unroll
    for (int i = 0; i < 4; i++) {
        int n = n0 + ty + i * 8, k = k0 + tx;
        B[(size_t)n * K + k] = __float2half_rn(t[tx * 33 + ty + i * 8]);
    }
}

// ---------------------------------------------------------------------------
// prep_kernel: ALL weight conversions + bias pack + LN1 in ONE launch.
// ---------------------------------------------------------------------------
#define PREP_BLOCKS 13828

__global__ __launch_bounds__(256)
void prep_kernel(const float* __restrict__ WQ, const float* __restrict__ WK,
                 const float* __restrict__ WV, const float* __restrict__ bQ,
                 const float* __restrict__ bK, const float* __restrict__ bV,
                 const float* __restrict__ WO, const float* __restrict__ Win,
                 const float* __restrict__ Wout, const float* __restrict__ resid,
                 const float* __restrict__ ln1w, const float* __restrict__ ln1b) {
    __shared__ float smf[32 * 65];
    int bid = blockIdx.x;
    int tid = threadIdx.x;

    if (bid < 4096) {
        int n0 = (bid & 127) * 32, k0 = (bid >> 7) * 32;
        wT_body(Win, g_win, DD, DMM, n0, k0, smf);
        return;
    }
    bid -= 4096;
    if (bid < 4096) {
        int n0 = (bid & 31) * 32, k0 = (bid >> 5) * 32;
        wT_body(Wout, g_wout, DMM, DD, n0, k0, smf);
        return;
    }
    bid -= 4096;
    if (bid < 4096) {
        ln_body(resid, ln1w, ln1b, g_x1, bid, smf);
        return;
    }
    bid -= 4096;
    if (bid < 1024) {
        int n0 = (bid & 31) * 32, k0 = (bid >> 5) * 32;
        wT_body(WO, g_wo, DD, DD, n0, k0, smf);
        return;
    }
    bid -= 1024;
    if (bid < 512) {
        int k0 = (bid & 31) * 32, h = bid >> 5;
        const float* Ws[3] = {WQ, WK, WV};
        for (int s = 0; s < 3; s++) {
            const float* src = Ws[s] + (size_t)h * DD * DHH + (size_t)k0 * DHH;
            #pragma unroll
            for (int it = 0; it < 8; it++) {
                int idx = tid + it * 256;
                smf[(idx >> 6) * 65 + (idx & 63)] = src[idx];
            }
            __syncthreads();
            #pragma unroll
            for (int it = 0; it < 8; it++) {
                int idx = tid + it * 256;
                int dh = idx >> 5, kk = idx & 31;
                size_t n = (size_t)s * DD + h * 64 + dh;
                g_wqkv[n * DD + k0 + kk] = __float2half_rn(smf[kk * 65 + dh]);
            }
            __syncthreads();
        }
        return;
    }
    bid -= 512;
    {
        int i = bid * 256 + tid;
        g_bqkv[i]          = bQ[i];
        g_bqkv[DD + i]     = bK[i];
        g_bqkv[2 * DD + i] = bV[i];
    }
}

__device__ __forceinline__ float gelu_tanh(float x) {
    float x3 = x * x * x;
    return 0.5f * x * (1.f + tanhf(0.7978845608028654f * (x + 0.044715f * x3)));
}

// ---------------------------------------------------------------------------
// LN2 (standalone; depends on rmid)
// ---------------------------------------------------------------------------
__global__ __launch_bounds__(256)
void ln_kernel(const float* __restrict__ x, const float* __restrict__ w,
               const float* __restrict__ b, __half* __restrict__ o) {
    __shared__ float red[32];
    ln_body(x, w, b, o, blockIdx.x, red);
}

// ---------------------------------------------------------------------------
// HMMA fp16 GEMM: de-phased 3-stage mbarrier ring (R14 winner).
// empty[s] now count 8: one arrive per warp (lane 0) — 32x less arrive traffic.
// ---------------------------------------------------------------------------
#define GOPD 18432                   // 128 rows * 144 B
#define GBUF (2 * GOPD)              // A | B per stage: 36864
#define GEMM_SMEM (3 * GBUF + 64)    // ring + mbarriers: 110656

__device__ __forceinline__ void gemm_load_nb(uint32_t dst, const char* const* src,
                                             size_t rowB, int k0b, int tid) {
    #pragma unroll
    for (int it = 0; it < 8; it++) {
        int c = tid + it * 256;
        int o = c >> 10, r = c & 1023, row = r >> 3, kc = r & 7;
        cp16(dst + o * GOPD + row * 144 + kc * 16,
             src[o] + (size_t)row * rowB + k0b + kc * 16);
    }
}

template <int EPI>
__global__ __launch_bounds__(256, 2)
void gemm_hmma(const __half* __restrict__ A, const __half* __restrict__ B,
               const float* __restrict__ bias, const float* __restrict__ R,
               float* __restrict__ Cf, __half* __restrict__ Ch,
               int M, int N, int K) {
    extern __shared__ char sm[];
    const uint32_t sb = smem_u32(sm);
    const uint32_t mb = sb + 3 * GBUF;          // full[0..2] @ +0/8/16, empty @ +24/32/40
    const int tid = threadIdx.x;
    const int wid = tid >> 5, lid = tid & 31;
    const int warp_m = wid >> 2, warp_n = wid & 3;

    if (tid == 0) {
        #pragma unroll
        for (int s = 0; s < 3; s++) {
            mbar_init(mb + s * 8, 256);         // full[s]: cp noinc per thread
            mbar_init(mb + 24 + s * 8, 8);      // empty[s]: lane0 per warp
        }
    }
    __syncthreads();

    const char* src[2];
    src[0] = (const char*)(A + (size_t)blockIdx.y * 128 * K);
    src[1] = (const char*)(B + (size_t)blockIdx.x * 128 * K);
    const size_t rowB = (size_t)K * 2;

    const int g = lid >> 3, li = lid & 7;
    const int a_row = (g & 1) * 8 + li, a_kb = (g >> 1) * 16;
    const int b_row = (g >> 1) * 8 + li, b_kb = (g & 1) * 16;

    float acc[4][4][4];
    #pragma unroll
    for (int mt = 0; mt < 4; mt++)
        #pragma unroll
        for (int nt = 0; nt < 4; nt++)
            #pragma unroll
            for (int e = 0; e < 4; e++) acc[mt][nt][e] = 0.f;

    const int T = K >> 6;   // K-tiles of 64 (>= 16 always)

    // prologue: produce tiles 0,1,2
    #pragma unroll
    for (int p = 0; p < 3; p++) {
        gemm_load_nb(sb + p * GBUF, src, rowB, p * 128, tid);
        cp_mbar_arrive(mb + p * 8);
    }

    for (int t = 0; t < T; t++) {
        const int s = t % 3;
        mbar_wait(mb + s * 8, (uint32_t)((t / 3) & 1));   // full[s]

        uint32_t buf = sb + s * GBUF;
        uint32_t aP = buf + (warp_m * 64 + a_row) * 144 + a_kb;
        uint32_t bP = buf + GOPD + (warp_n * 32 + b_row) * 144 + b_kb;

        #pragma unroll
        for (int kk = 0; kk < 4; kk++) {
            uint32_t bh[4][2];
            ldsm4(bh[0][0], bh[0][1], bh[1][0], bh[1][1], bP + kk * 32);
            ldsm4(bh[2][0], bh[2][1], bh[3][0], bh[3][1], bP + 16 * 144 + kk * 32);
            #pragma unroll
            for (int mt = 0; mt < 4; mt++) {
                uint32_t ah[4];
                ldsm4(ah[0], ah[1], ah[2], ah[3], aP + mt * 16 * 144 + kk * 32);
                #pragma unroll
                for (int nt = 0; nt < 4; nt++)
                    mma16816(acc[mt][nt], ah, bh[nt]);
            }
        }

        if (lid == 0) mbar_arrive(mb + 24 + s * 8);       // empty[s], warp-level

        if (t + 3 < T) {
            mbar_wait(mb + 24 + s * 8, (uint32_t)((t / 3) & 1));
            gemm_load_nb(buf, src, rowB, (t + 3) * 128, tid);
            cp_mbar_arrive(mb + s * 8);
        }
    }

    const int group = lid >> 2, t4 = lid & 3;
    const size_t rbase = (size_t)blockIdx.y * 128 + warp_m * 64;
    const int cbase = blockIdx.x * 128 + warp_n * 32;
    #pragma unroll
    for (int mt = 0; mt < 4; mt++) {
        size_t r0 = rbase + mt * 16 + group;
        size_t r1 = r0 + 8;
        #pragma unroll
        for (int nt = 0; nt < 4; nt++) {
            int col = cbase + nt * 8 + t4 * 2;
            float* c = acc[mt][nt];
            float b0 = bias[col], b1 = bias[col + 1];
            float x0 = c[0] + b0, x1 = c[1] + b1;
            float x2 = c[2] + b0, x3 = c[3] + b1;
            if (EPI == 1 || EPI == 3) {
                if (EPI == 1) {
                    x0 = gelu_tanh(x0); x1 = gelu_tanh(x1);
                    x2 = gelu_tanh(x2); x3 = gelu_tanh(x3);
                } else {
                    float qsc = (blockIdx.x < 8) ? 0.125f * LOG2E : 1.0f;
                    x0 *= qsc; x1 *= qsc; x2 *= qsc; x3 *= qsc;
                }
                *(__half2*)(Ch + r0 * N + col) = __floats2half2_rn(x0, x1);
                *(__half2*)(Ch + r1 * N + col) = __floats2half2_rn(x2, x3);
            } else {
                float2 ra = *(const float2*)(R + r0 * N + col);
                float2 rb = *(const float2*)(R + r1 * N + col);
                x0 += ra.x; x1 += ra.y; x2 += rb.x; x3 += rb.y;
                float2 va; va.x = x0; va.y = x1;
                float2 vb; vb.x = x2; vb.y = x3;
                *(float2*)(Cf + r0 * N + col) = va;
                *(float2*)(Cf + r1 * N + col) = vb;
            }
        }
    }
}

// ---------------------------------------------------------------------------
// flash2: tensor-core causal flash attention, NOW de-phased like the GEMM:
// 3-stage K/V ring with full/empty mbarriers instead of __syncthreads/tile.
// Warps drift across tiles (they are row-independent; only the K/V ring
// couples them). Q staged via commit/wait_group (separate path).
// full[s]: 256 noinc cp arrivals ; empty[s]: 8 arrivals (lane 0 per warp).
// ---------------------------------------------------------------------------
#define FPB 144
#define FL_KV 18432
#define FL_TILE 9216
#define FL_BUF 18432
#define FLASH2_SMEM (FL_KV + 3 * FL_BUF + 64)   // +mbarriers: 73792

__device__ __forceinline__ void fl_load_kv_nb(uint32_t sb, const __half* base,
                                              int kt, int bi, int tid) {
    uint32_t dst0 = sb + FL_KV + bi * FL_BUF;
    #pragma unroll
    for (int it = 0; it < 4; it++) {
        int idx = tid + it * 256;
        int reg = idx >> 9;
        int r = idx & 511;
        int row = r >> 3, c = r & 7;
        const __half* s = base + (size_t)(kt * 64 + row) * QKVN + DD + reg * DD + c * 8;
        cp16(dst0 + reg * FL_TILE + row * FPB + c * 16, s);
    }
}

__global__ __launch_bounds__(256, 2)
void flash2(const __half* __restrict__ qkv, __half* __restrict__ z) {
    extern __shared__ char sm[];
    const uint32_t sb = smem_u32(sm);
    const uint32_t mb = sb + FL_KV + 3 * FL_BUF;   // full@+0/8/16, empty@+24/32/40
    const int tid = threadIdx.x, wid = tid >> 5, lid = tid & 31;
    const int qt = (int)gridDim.x - 1 - (int)blockIdx.x;
    const int h = blockIdx.y, b = blockIdx.z;

    const __half* base = qkv + (size_t)b * SS * QKVN + h * 64;
    const int nkt = 2 * qt + 2;

    if (tid == 0) {
        #pragma unroll
        for (int s = 0; s < 3; s++) {
            mbar_init(mb + s * 8, 256);
            mbar_init(mb + 24 + s * 8, 8);
        }
    }
    __syncthreads();   // mbarrier init visible before any arrive

    // Q tile (own commit group), then prologue K/V tiles with noinc arrivals
    #pragma unroll
    for (int it = 0; it < 4; it++) {
        int idx = tid + it * 256;
        int row = idx >> 3, c = idx & 7;
        cp16(sb + row * FPB + c * 16, base + (size_t)(qt * 128 + row) * QKVN + c * 8);
    }
    CP_COMMIT();
    #pragma unroll
    for (int p = 0; p < 3; p++) {
        if (p < nkt) {
            fl_load_kv_nb(sb, base, p, p, tid);
            cp_mbar_arrive(mb + p * 8);
        }
    }

    asm volatile("cp.async.wait_group 0;" ::: "memory");  // Q group done
    __syncthreads();                                      // Q visible to all

    const int g2 = lid >> 3, li = lid & 7;
    const int a_row = (g2 & 1) * 8 + li, a_kb = (g2 >> 1) * 16;
    const uint32_t qa = sb + (wid * 16 + a_row) * FPB + a_kb;
    uint32_t qh[4][4];
    #pragma unroll
    for (int kc = 0; kc < 4; kc++)
        ldsm4(qh[kc][0], qh[kc][1], qh[kc][2], qh[kc][3], qa + kc * 32);

    float o[8][4];
    #pragma unroll
    for (int nt = 0; nt < 8; nt++)
        #pragma unroll
        for (int e = 0; e < 4; e++) o[nt][e] = 0.f;
    float m0 = -1e30f, m1 = -1e30f, l0 = 0.f, l1 = 0.f;

    const int gq = lid >> 2, t4 = lid & 3;
    const int row0g = qt * 128 + wid * 16 + gq;
    const int row1g = row0g + 8;

    const uint32_t kb_off = (uint32_t)(((g2 >> 1) * 8 + li) * FPB + (g2 & 1) * 16);
    const uint32_t v_off  = (uint32_t)(((g2 & 1) * 8 + li) * FPB + (g2 >> 1) * 16);

    for (int kt = 0; kt < nkt; kt++) {
        const int s = kt % 3;
        mbar_wait(mb + s * 8, (uint32_t)((kt / 3) & 1));   // full[s]
        const uint32_t buf = sb + FL_KV + s * FL_BUF;

        float sc[8][4];
        #pragma unroll
        for (int nt = 0; nt < 8; nt++)
            #pragma unroll
            for (int e = 0; e < 4; e++) sc[nt][e] = 0.f;

        #pragma unroll
        for (int kc = 0; kc < 4; kc++) {
            #pragma unroll
            for (int ntp = 0; ntp < 4; ntp++) {
                uint32_t ka = buf + kb_off + ntp * 16 * FPB + kc * 32;
                uint32_t h0, h1, h2, h3;
                ldsm4(h0, h1, h2, h3, ka);
                mma2(sc[2 * ntp],     qh[kc], h0, h1);
                mma2(sc[2 * ntp + 1], qh[kc], h2, h3);
            }
        }

        if (kt >= 2 * qt) {
            int colb = kt * 64 + 2 * t4;
            #pragma unroll
            for (int nt = 0; nt < 8; nt++) {
                int c0 = colb + nt * 8, c1 = c0 + 1;
                if (c0 > row0g) sc[nt][0] = -1e30f;
                if (c1 > row0g) sc[nt][1] = -1e30f;
                if (c0 > row1g) sc[nt][2] = -1e30f;
                if (c1 > row1g) sc[nt][3] = -1e30f;
            }
        }

        float tm0 = -1e30f, tm1 = -1e30f;
        #pragma unroll
        for (int nt = 0; nt < 8; nt++) {
            tm0 = fmaxf(tm0, fmaxf(sc[nt][0], sc[nt][1]));
            tm1 = fmaxf(tm1, fmaxf(sc[nt][2], sc[nt][3]));
        }
        tm0 = fmaxf(tm0, __shfl_xor_sync(0xffffffffu, tm0, 1));
        tm0 = fmaxf(tm0, __shfl_xor_sync(0xffffffffu, tm0, 2));
        tm1 = fmaxf(tm1, __shfl_xor_sync(0xffffffffu, tm1, 1));
        tm1 = fmaxf(tm1, __shfl_xor_sync(0xffffffffu, tm1, 2));
        float mn0 = fmaxf(m0, tm0), mn1 = fmaxf(m1, tm1);
        float al0 = exp2f(m0 - mn0), al1 = exp2f(m1 - mn1);
        m0 = mn0; m1 = mn1;

        float rs0 = 0.f, rs1 = 0.f;
        #pragma unroll
        for (int nt = 0; nt < 8; nt++) {
            sc[nt][0] = exp2f(sc[nt][0] - mn0); rs0 += sc[nt][0];
            sc[nt][1] = exp2f(sc[nt][1] - mn0); rs0 += sc[nt][1];
            sc[nt][2] = exp2f(sc[nt][2] - mn1); rs1 += sc[nt][2];
            sc[nt][3] = exp2f(sc[nt][3] - mn1); rs1 += sc[nt][3];
        }
        rs0 += __shfl_xor_sync(0xffffffffu, rs0, 1);
        rs0 += __shfl_xor_sync(0xffffffffu, rs0, 2);
        rs1 += __shfl_xor_sync(0xffffffffu, rs1, 1);
        rs1 += __shfl_xor_sync(0xffffffffu, rs1, 2);
        l0 = l0 * al0 + rs0;
        l1 = l1 * al1 + rs1;
        #pragma unroll
        for (int nt = 0; nt < 8; nt++) {
            o[nt][0] *= al0; o[nt][1] *= al0;
            o[nt][2] *= al1; o[nt][3] *= al1;
        }

        uint32_t pa[4][4];
        #pragma unroll
        for (int kc = 0; kc < 4; kc++) {
            pa[kc][0] = f2h2(sc[2 * kc][0],     sc[2 * kc][1]);
            pa[kc][1] = f2h2(sc[2 * kc][2],     sc[2 * kc][3]);
            pa[kc][2] = f2h2(sc[2 * kc + 1][0], sc[2 * kc + 1][1]);
            pa[kc][3] = f2h2(sc[2 * kc + 1][2], sc[2 * kc + 1][3]);
        }

        #pragma unroll
        for (int kc = 0; kc < 4; kc++) {
            #pragma unroll
            for (int ntp = 0; ntp < 4; ntp++) {
                uint32_t va = buf + FL_TILE + kc * 16 * FPB + ntp * 32 + v_off;
                uint32_t h0, h1, h2, h3;
                ldsm4t(h0, h1, h2, h3, va);
                mma2(o[2 * ntp],     pa[kc], h0, h1);
                mma2(o[2 * ntp + 1], pa[kc], h2, h3);
            }
        }

        if (lid == 0) mbar_arrive(mb + 24 + s * 8);        // empty[s]

        if (kt + 3 < nkt) {
            mbar_wait(mb + 24 + s * 8, (uint32_t)((kt / 3) & 1));
            fl_load_kv_nb(sb, base, kt + 3, s, tid);
            cp_mbar_arrive(mb + s * 8);
        }
    }

    float iv0 = 1.f / l0, iv1 = 1.f / l1;
    size_t r0 = (size_t)b * SS + qt * 128 + wid * 16 + gq;
    size_t r1 = r0 + 8;
    #pragma unroll
    for (int nt = 0; nt < 8; nt++) {
        int col = h * 64 + nt * 8 + 2 * t4;
        *(__half2*)(z + r0 * DD + col) = __floats2half2_rn(o[nt][0] * iv0, o[nt][1] * iv0);
        *(__half2*)(z + r1 * DD + col) = __floats2half2_rn(o[nt][2] * iv1, o[nt][3] * iv1);
    }
}

// ---------------------------------------------------------------------------
// Launch
// ---------------------------------------------------------------------------
extern "C" void kernel_launch(void* const* d_in, const int* in_sizes, int n_in,
                              void* d_out, int out_size) {
    (void)in_sizes; (void)n_in; (void)out_size;
    const float* resid_pre = (const float*)d_in[0];
    const float* ln1_w = (const float*)d_in[1];
    const float* ln1_b = (const float*)d_in[2];
    const float* W_Q   = (const float*)d_in[3];
    const float* W_K   = (const float*)d_in[4];
    const float* W_V   = (const float*)d_in[5];
    const float* W_O   = (const float*)d_in[6];
    const float* b_Q   = (const float*)d_in[7];
    const float* b_K   = (const float*)d_in[8];
    const float* b_V   = (const float*)d_in[9];
    const float* b_O   = (const float*)d_in[10];
    const float* ln2_w = (const float*)d_in[11];
    const float* ln2_b = (const float*)d_in[12];
    const float* W_in  = (const float*)d_in[13];
    const float* b_in  = (const float*)d_in[14];
    const float* W_out = (const float*)d_in[15];
    const float* b_out = (const float*)d_in[16];
    float* out = (float*)d_out;

    __half *p_x1, *p_wqkv, *p_qkv, *p_z, *p_wo, *p_x2, *p_win, *p_h, *p_wout;
    float *p_bqkv, *p_rmid;
    cudaGetSymbolAddress((void**)&p_x1, g_x1);
    cudaGetSymbolAddress((void**)&p_wqkv, g_wqkv);
    cudaGetSymbolAddress((void**)&p_bqkv, g_bqkv);
    cudaGetSymbolAddress((void**)&p_qkv, g_qkv);
    cudaGetSymbolAddress((void**)&p_z, g_z);
    cudaGetSymbolAddress((void**)&p_wo, g_wo);
    cudaGetSymbolAddress((void**)&p_rmid, g_rmid);
    cudaGetSymbolAddress((void**)&p_x2, g_x2);
    cudaGetSymbolAddress((void**)&p_win, g_win);
    cudaGetSymbolAddress((void**)&p_h, g_h);
    cudaGetSymbolAddress((void**)&p_wout, g_wout);

    cudaFuncSetAttribute(flash2, cudaFuncAttributeMaxDynamicSharedMemorySize, FLASH2_SMEM);
    cudaFuncSetAttribute(gemm_hmma<1>, cudaFuncAttributeMaxDynamicSharedMemorySize, GEMM_SMEM);
    cudaFuncSetAttribute(gemm_hmma<2>, cudaFuncAttributeMaxDynamicSharedMemorySize, GEMM_SMEM);
    cudaFuncSetAttribute(gemm_hmma<3>, cudaFuncAttributeMaxDynamicSharedMemorySize, GEMM_SMEM);

    // ALL prep (weight conversions + bias pack + LN1) in one launch
    prep_kernel<<<PREP_BLOCKS, 256>>>(W_Q, W_K, W_V, b_Q, b_K, b_V,
                                      W_O, W_in, W_out,
                                      resid_pre, ln1_w, ln1_b);

    // QKV projection -> fp16 (Q scaled by 0.125*log2e)
    gemm_hmma<3><<<dim3(QKVN / 128, BSS / 128), 256, GEMM_SMEM>>>(
        p_x1, p_wqkv, p_bqkv, nullptr, nullptr, p_qkv, BSS, QKVN, DD);

    // flash attention (tensor cores, base-2 softmax, de-phased ring) -> z
    flash2<<<dim3(SS / 128, HH, BB), 256, FLASH2_SMEM>>>(p_qkv, p_z);

    // O projection + residual -> rmid fp32
    gemm_hmma<2><<<dim3(DD / 128, BSS / 128), 256, GEMM_SMEM>>>(
        p_z, p_wo, b_O, resid_pre, p_rmid, nullptr, BSS, DD, DD);

    // LN2
    ln_kernel<<<BSS, 256>>>(p_rmid, ln2_w, ln2_b, p_x2);

    // MLP in + gelu -> h fp16
    gemm_hmma<1><<<dim3(DMM / 128, BSS / 128), 256, GEMM_SMEM>>>(
        p_x2, p_win, b_in, nullptr, nullptr, p_h, BSS, DMM, DD);

    // MLP out + residual -> out fp32
    gemm_hmma<2><<<dim3(DD / 128, BSS / 128), 256, GEMM_SMEM>>>(
        p_h, p_wout, b_out, p_rmid, out, nullptr, BSS, DD, DMM);
}

// round 16
// speedup vs baseline: 1.2039x; 1.0049x over previous
#include <cuda_runtime.h>
#include <cuda_fp16.h>
#include <cstdint>
#include <cstddef>

// ---------------------------------------------------------------------------
// Problem constants
// ---------------------------------------------------------------------------
#define BB   2
#define SS   2048
#define DD   1024
#define HH   16
#define DHH  64
#define DMM  4096
#define BSS  (BB * SS)          // 4096 rows
#define QKVN (3 * DD)           // 3072
#define LN_EPS 1e-5f
#define LOG2E 1.4426950408889634f

// ---------------------------------------------------------------------------
// Scratch (static device globals; fp16 single-precision path, fp32 accum)
// ---------------------------------------------------------------------------
__device__ __half g_x1[BSS * DD];                 // LN1 out
__device__ __half g_wqkv[QKVN * DD];              // [N=3072,K=1024]
__device__ float  g_bqkv[QKVN];
__device__ __half g_qkv[(size_t)BSS * QKVN];      // q(0.125*log2e-folded)|k|v
__device__ __half g_z[BSS * DD];                  // attention out
__device__ __half g_wo[DD * DD];                  // [N=1024,K=1024]
__device__ float  g_rmid[BSS * DD];
__device__ __half g_x2[BSS * DD];                 // LN2 out
__device__ __half g_win[DMM * DD];                // [N=4096,K=1024]
__device__ __half g_h[(size_t)BSS * DMM];         // MLP hidden
__device__ __half g_wout[DD * DMM];               // [N=1024,K=4096]

// ---------------------------------------------------------------------------
// PTX helpers (baseline ISA: ldmatrix / mma.sync / cp.async / mbarrier)
// ---------------------------------------------------------------------------
__device__ __forceinline__ uint32_t smem_u32(const void* p) {
    uint32_t a;
    asm("{ .reg .u64 t; cvta.to.shared.u64 t, %1; cvt.u32.u64 %0, t; }" : "=r"(a) : "l"(p));
    return a;
}
__device__ __forceinline__ void ldsm4(uint32_t& r0, uint32_t& r1, uint32_t& r2,
                                      uint32_t& r3, uint32_t a) {
    asm volatile("ldmatrix.sync.aligned.m8n8.x4.shared.b16 {%0,%1,%2,%3}, [%4];"
                 : "=r"(r0), "=r"(r1), "=r"(r2), "=r"(r3) : "r"(a));
}
__device__ __forceinline__ void ldsm4t(uint32_t& r0, uint32_t& r1, uint32_t& r2,
                                       uint32_t& r3, uint32_t a) {
    asm volatile("ldmatrix.sync.aligned.m8n8.x4.trans.shared.b16 {%0,%1,%2,%3}, [%4];"
                 : "=r"(r0), "=r"(r1), "=r"(r2), "=r"(r3) : "r"(a));
}
__device__ __forceinline__ void mma16816(float* c, const uint32_t* a, const uint32_t* b) {
    asm volatile(
        "mma.sync.aligned.m16n8k16.row.col.f32.f16.f16.f32 "
        "{%0,%1,%2,%3},{%4,%5,%6,%7},{%8,%9},{%0,%1,%2,%3};"
        : "+f"(c[0]), "+f"(c[1]), "+f"(c[2]), "+f"(c[3])
        : "r"(a[0]), "r"(a[1]), "r"(a[2]), "r"(a[3]), "r"(b[0]), "r"(b[1]));
}
__device__ __forceinline__ void mma2(float* c, const uint32_t* a, uint32_t b0, uint32_t b1) {
    asm volatile(
        "mma.sync.aligned.m16n8k16.row.col.f32.f16.f16.f32 "
        "{%0,%1,%2,%3},{%4,%5,%6,%7},{%8,%9},{%0,%1,%2,%3};"
        : "+f"(c[0]), "+f"(c[1]), "+f"(c[2]), "+f"(c[3])
        : "r"(a[0]), "r"(a[1]), "r"(a[2]), "r"(a[3]), "r"(b0), "r"(b1));
}
__device__ __forceinline__ void cp16(uint32_t d, const void* s) {
    asm volatile("cp.async.cg.shared.global [%0], [%1], 16;" :: "r"(d), "l"(s) : "memory");
}
#define CP_COMMIT() asm volatile("cp.async.commit_group;" ::: "memory")

__device__ __forceinline__ void mbar_init(uint32_t a, uint32_t cnt) {
    asm volatile("mbarrier.init.shared.b64 [%0], %1;" :: "r"(a), "r"(cnt) : "memory");
}
__device__ __forceinline__ void mbar_arrive(uint32_t a) {
    asm volatile("mbarrier.arrive.shared.b64 _, [%0];" :: "r"(a) : "memory");
}
__device__ __forceinline__ void cp_mbar_arrive(uint32_t a) {
    asm volatile("cp.async.mbarrier.arrive.noinc.shared.b64 [%0];" :: "r"(a) : "memory");
}
__device__ __forceinline__ void mbar_wait(uint32_t a, uint32_t parity) {
    asm volatile(
        "{\n\t.reg .pred P;\n\t"
        "WL_%=:\n\t"
        "mbarrier.try_wait.parity.acquire.cta.shared::cta.b64 P, [%0], %1, 0x989680;\n\t"
        "@P bra.uni WD_%=;\n\t"
        "bra.uni WL_%=;\n\t"
        "WD_%=:\n\t}"
        :: "r"(a), "r"(parity) : "memory");
}

__device__ __forceinline__ uint32_t f2h2(float a, float b) {
    __half2 h = __floats2half2_rn(a, b);
    return *(uint32_t*)&h;
}

// ---------------------------------------------------------------------------
// Block reduction
// ---------------------------------------------------------------------------
__device__ __forceinline__ float block_sum(float v, float* red) {
    __syncthreads();
    int lane = threadIdx.x & 31, wid = threadIdx.x >> 5;
    #pragma unroll
    for (int o = 16; o > 0; o >>= 1) v += __shfl_xor_sync(0xffffffffu, v, o);
    if (lane == 0) red[wid] = v;
    __syncthreads();
    float t = (threadIdx.x < (blockDim.x >> 5)) ? red[threadIdx.x] : 0.f;
    if (wid == 0) {
        #pragma unroll
        for (int o = 16; o > 0; o >>= 1) t += __shfl_xor_sync(0xffffffffu, t, o);
        if (lane == 0) red[0] = t;
    }
    __syncthreads();
    return red[0];
}

// ---------------------------------------------------------------------------
// LN row body (register-resident, 256 threads x float4)
// ---------------------------------------------------------------------------
__device__ __forceinline__ void ln_body(const float* __restrict__ x,
                                        const float* __restrict__ w,
                                        const float* __restrict__ b,
                                        __half* __restrict__ o, int r, float* red) {
    int tid = threadIdx.x;
    float4 v = ((const float4*)(x + (size_t)r * DD))[tid];
    float s = block_sum(v.x + v.y + v.z + v.w, red);
    float mean = s * (1.f / DD);
    float dx = v.x - mean, dy = v.y - mean, dz = v.z - mean, dw = v.w - mean;
    float q = block_sum(dx * dx + dy * dy + dz * dz + dw * dw, red);
    float inv = rsqrtf(q * (1.f / DD) + LN_EPS);
    float4 w4 = ((const float4*)w)[tid];
    float4 b4 = ((const float4*)b)[tid];
    __half2 h0 = __floats2half2_rn(dx * inv * w4.x + b4.x, dy * inv * w4.y + b4.y);
    __half2 h1 = __floats2half2_rn(dz * inv * w4.z + b4.z, dw * inv * w4.w + b4.w);
    uint2 pk; pk.x = *(uint32_t*)&h0; pk.y = *(uint32_t*)&h1;
    ((uint2*)(o + (size_t)r * DD))[tid] = pk;
}

// conv_wT body: W fp32 [K,N] tile -> B fp16 [N,K]
__device__ __forceinline__ void wT_body(const float* __restrict__ W,
                                        __half* __restrict__ B, int K, int N,
                                        int n0, int k0, float* t /*32x33*/) {
    int tid = threadIdx.x;
    int tx = tid & 31, ty = tid >> 5;
    #pragma unroll
    for (int i = 0; i < 4; i++)
        t[(ty + i * 8) * 33 + tx] = W[(size_t)(k0 + ty + i * 8) * N + n0 + tx];
    __syncthreads();
    #pragma unroll
    for (int i = 0; i < 4; i++) {
        int n = n0 + ty + i * 8, k = k0 + tx;
        B[(size_t)n * K + k] = __float2half_rn(t[tx * 33 + ty + i * 8]);
    }
}

// ---------------------------------------------------------------------------
// prep_kernel: ALL weight conversions + bias pack + LN1 in ONE launch.
// ---------------------------------------------------------------------------
#define PREP_BLOCKS 13828

__global__ __launch_bounds__(256)
void prep_kernel(const float* __restrict__ WQ, const float* __restrict__ WK,
                 const float* __restrict__ WV, const float* __restrict__ bQ,
                 const float* __restrict__ bK, const float* __restrict__ bV,
                 const float* __restrict__ WO, const float* __restrict__ Win,
                 const float* __restrict__ Wout, const float* __restrict__ resid,
                 const float* __restrict__ ln1w, const float* __restrict__ ln1b) {
    __shared__ float smf[32 * 65];
    int bid = blockIdx.x;
    int tid = threadIdx.x;

    if (bid < 4096) {
        int n0 = (bid & 127) * 32, k0 = (bid >> 7) * 32;
        wT_body(Win, g_win, DD, DMM, n0, k0, smf);
        return;
    }
    bid -= 4096;
    if (bid < 4096) {
        int n0 = (bid & 31) * 32, k0 = (bid >> 5) * 32;
        wT_body(Wout, g_wout, DMM, DD, n0, k0, smf);
        return;
    }
    bid -= 4096;
    if (bid < 4096) {
        ln_body(resid, ln1w, ln1b, g_x1, bid, smf);
        return;
    }
    bid -= 4096;
    if (bid < 1024) {
        int n0 = (bid & 31) * 32, k0 = (bid >> 5) * 32;
        wT_body(WO, g_wo, DD, DD, n0, k0, smf);
        return;
    }
    bid -= 1024;
    if (bid < 512) {
        int k0 = (bid & 31) * 32, h = bid >> 5;
        const float* Ws[3] = {WQ, WK, WV};
        for (int s = 0; s < 3; s++) {
            const float* src = Ws[s] + (size_t)h * DD * DHH + (size_t)k0 * DHH;
            #pragma unroll
            for (int it = 0; it < 8; it++) {
                int idx = tid + it * 256;
                smf[(idx >> 6) * 65 + (idx & 63)] = src[idx];
            }
            __syncthreads();
            #pragma unroll
            for (int it = 0; it < 8; it++) {
                int idx = tid + it * 256;
                int dh = idx >> 5, kk = idx & 31;
                size_t n = (size_t)s * DD + h * 64 + dh;
                g_wqkv[n * DD + k0 + kk] = __float2half_rn(smf[kk * 65 + dh]);
            }
            __syncthreads();
        }
        return;
    }
    bid -= 512;
    {
        int i = bid * 256 + tid;
        g_bqkv[i]          = bQ[i];
        g_bqkv[DD + i]     = bK[i];
        g_bqkv[2 * DD + i] = bV[i];
    }
}

__device__ __forceinline__ float gelu_tanh(float x) {
    float x3 = x * x * x;
    return 0.5f * x * (1.f + tanhf(0.7978845608028654f * (x + 0.044715f * x3)));
}

// ---------------------------------------------------------------------------
// LN2 (standalone; depends on rmid)
// ---------------------------------------------------------------------------
__global__ __launch_bounds__(256)
void ln_kernel(const float* __restrict__ x, const float* __restrict__ w,
               const float* __restrict__ b, __half* __restrict__ o) {
    __shared__ float red[32];
    ln_body(x, w, b, o, blockIdx.x, red);
}

// ---------------------------------------------------------------------------
// HMMA fp16 GEMM: de-phased 3-stage mbarrier ring (R15 winner) PLUS
// software-pipelined B fragments: bh for kk+1 is ldsm'd BEFORE the MMA block
// of kk (ping/pong buffers), overlapping smem-read latency with tensor work.
// Hypothesis test: latency-bound (win) vs legacy-HMMA floor (neutral).
// ---------------------------------------------------------------------------
#define GOPD 18432                   // 128 rows * 144 B
#define GBUF (2 * GOPD)              // A | B per stage: 36864
#define GEMM_SMEM (3 * GBUF + 64)    // ring + mbarriers: 110656

__device__ __forceinline__ void gemm_load_nb(uint32_t dst, const char* const* src,
                                             size_t rowB, int k0b, int tid) {
    #pragma unroll
    for (int it = 0; it < 8; it++) {
        int c = tid + it * 256;
        int o = c >> 10, r = c & 1023, row = r >> 3, kc = r & 7;
        cp16(dst + o * GOPD + row * 144 + kc * 16,
             src[o] + (size_t)row * rowB + k0b + kc * 16);
    }
}

template <int EPI>
__global__ __launch_bounds__(256, 2)
void gemm_hmma(const __half* __restrict__ A, const __half* __restrict__ B,
               const float* __restrict__ bias, const float* __restrict__ R,
               float* __restrict__ Cf, __half* __restrict__ Ch,
               int M, int N, int K) {
    extern __shared__ char sm[];
    const uint32_t sb = smem_u32(sm);
    const uint32_t mb = sb + 3 * GBUF;          // full[0..2] @ +0/8/16, empty @ +24/32/40
    const int tid = threadIdx.x;
    const int wid = tid >> 5, lid = tid & 31;
    const int warp_m = wid >> 2, warp_n = wid & 3;

    if (tid == 0) {
        #pragma unroll
        for (int s = 0; s < 3; s++) {
            mbar_init(mb + s * 8, 256);         // full[s]: cp noinc per thread
            mbar_init(mb + 24 + s * 8, 8);      // empty[s]: lane0 per warp
        }
    }
    __syncthreads();

    const char* src[2];
    src[0] = (const char*)(A + (size_t)blockIdx.y * 128 * K);
    src[1] = (const char*)(B + (size_t)blockIdx.x * 128 * K);
    const size_t rowB = (size_t)K * 2;

    const int g = lid >> 3, li = lid & 7;
    const int a_row = (g & 1) * 8 + li, a_kb = (g >> 1) * 16;
    const int b_row = (g >> 1) * 8 + li, b_kb = (g & 1) * 16;

    float acc[4][4][4];
    #pragma unroll
    for (int mt = 0; mt < 4; mt++)
        #pragma unroll
        for (int nt = 0; nt < 4; nt++)
            #pragma unroll
            for (int e = 0; e < 4; e++) acc[mt][nt][e] = 0.f;

    const int T = K >> 6;   // K-tiles of 64 (>= 16 always)

    // prologue: produce tiles 0,1,2
    #pragma unroll
    for (int p = 0; p < 3; p++) {
        gemm_load_nb(sb + p * GBUF, src, rowB, p * 128, tid);
        cp_mbar_arrive(mb + p * 8);
    }

    for (int t = 0; t < T; t++) {
        const int s = t % 3;
        mbar_wait(mb + s * 8, (uint32_t)((t / 3) & 1));   // full[s]

        uint32_t buf = sb + s * GBUF;
        uint32_t aP = buf + (warp_m * 64 + a_row) * 144 + a_kb;
        uint32_t bP = buf + GOPD + (warp_n * 32 + b_row) * 144 + b_kb;

        // software pipeline: ping/pong B fragments, next-kk ldsm before MMAs
        uint32_t bh[2][4][2];
        ldsm4(bh[0][0][0], bh[0][0][1], bh[0][1][0], bh[0][1][1], bP);
        ldsm4(bh[0][2][0], bh[0][2][1], bh[0][3][0], bh[0][3][1], bP + 16 * 144);

        #pragma unroll
        for (int kk = 0; kk < 4; kk++) {
            const int cur = kk & 1, nxt = cur ^ 1;
            if (kk < 3) {
                ldsm4(bh[nxt][0][0], bh[nxt][0][1], bh[nxt][1][0], bh[nxt][1][1],
                      bP + (kk + 1) * 32);
                ldsm4(bh[nxt][2][0], bh[nxt][2][1], bh[nxt][3][0], bh[nxt][3][1],
                      bP + 16 * 144 + (kk + 1) * 32);
            }
            #pragma unroll
            for (int mt = 0; mt < 4; mt++) {
                uint32_t ah[4];
                ldsm4(ah[0], ah[1], ah[2], ah[3], aP + mt * 16 * 144 + kk * 32);
                #pragma unroll
                for (int nt = 0; nt < 4; nt++)
                    mma16816(acc[mt][nt], ah, bh[cur][nt]);
            }
        }

        if (lid == 0) mbar_arrive(mb + 24 + s * 8);       // empty[s], warp-level

        if (t + 3 < T) {
            mbar_wait(mb + 24 + s * 8, (uint32_t)((t / 3) & 1));
            gemm_load_nb(buf, src, rowB, (t + 3) * 128, tid);
            cp_mbar_arrive(mb + s * 8);
        }
    }

    const int group = lid >> 2, t4 = lid & 3;
    const size_t rbase = (size_t)blockIdx.y * 128 + warp_m * 64;
    const int cbase = blockIdx.x * 128 + warp_n * 32;
    #pragma unroll
    for (int mt = 0; mt < 4; mt++) {
        size_t r0 = rbase + mt * 16 + group;
        size_t r1 = r0 + 8;
        #pragma unroll
        for (int nt = 0; nt < 4; nt++) {
            int col = cbase + nt * 8 + t4 * 2;
            float* c = acc[mt][nt];
            float b0 = bias[col], b1 = bias[col + 1];
            float x0 = c[0] + b0, x1 = c[1] + b1;
            float x2 = c[2] + b0, x3 = c[3] + b1;
            if (EPI == 1 || EPI == 3) {
                if (EPI == 1) {
                    x0 = gelu_tanh(x0); x1 = gelu_tanh(x1);
                    x2 = gelu_tanh(x2); x3 = gelu_tanh(x3);
                } else {
                    float qsc = (blockIdx.x < 8) ? 0.125f * LOG2E : 1.0f;
                    x0 *= qsc; x1 *= qsc; x2 *= qsc; x3 *= qsc;
                }
                *(__half2*)(Ch + r0 * N + col) = __floats2half2_rn(x0, x1);
                *(__half2*)(Ch + r1 * N + col) = __floats2half2_rn(x2, x3);
            } else {
                float2 ra = *(const float2*)(R + r0 * N + col);
                float2 rb = *(const float2*)(R + r1 * N + col);
                x0 += ra.x; x1 += ra.y; x2 += rb.x; x3 += rb.y;
                float2 va; va.x = x0; va.y = x1;
                float2 vb; vb.x = x2; vb.y = x3;
                *(float2*)(Cf + r0 * N + col) = va;
                *(float2*)(Cf + r1 * N + col) = vb;
            }
        }
    }
}

// ---------------------------------------------------------------------------
// flash2: tensor-core causal flash attention, de-phased ring (R15 winner).
// ---------------------------------------------------------------------------
#define FPB 144
#define FL_KV 18432
#define FL_TILE 9216
#define FL_BUF 18432
#define FLASH2_SMEM (FL_KV + 3 * FL_BUF + 64)   // 73792

__device__ __forceinline__ void fl_load_kv_nb(uint32_t sb, const __half* base,
                                              int kt, int bi, int tid) {
    uint32_t dst0 = sb + FL_KV + bi * FL_BUF;
    #pragma unroll
    for (int it = 0; it < 4; it++) {
        int idx = tid + it * 256;
        int reg = idx >> 9;
        int r = idx & 511;
        int row = r >> 3, c = r & 7;
        const __half* s = base + (size_t)(kt * 64 + row) * QKVN + DD + reg * DD + c * 8;
        cp16(dst0 + reg * FL_TILE + row * FPB + c * 16, s);
    }
}

__global__ __launch_bounds__(256, 2)
void flash2(const __half* __restrict__ qkv, __half* __restrict__ z) {
    extern __shared__ char sm[];
    const uint32_t sb = smem_u32(sm);
    const uint32_t mb = sb + FL_KV + 3 * FL_BUF;
    const int tid = threadIdx.x, wid = tid >> 5, lid = tid & 31;
    const int qt = (int)gridDim.x - 1 - (int)blockIdx.x;
    const int h = blockIdx.y, b = blockIdx.z;

    const __half* base = qkv + (size_t)b * SS * QKVN + h * 64;
    const int nkt = 2 * qt + 2;

    if (tid == 0) {
        #pragma unroll
        for (int s = 0; s < 3; s++) {
            mbar_init(mb + s * 8, 256);
            mbar_init(mb + 24 + s * 8, 8);
        }
    }
    __syncthreads();

    #pragma unroll
    for (int it = 0; it < 4; it++) {
        int idx = tid + it * 256;
        int row = idx >> 3, c = idx & 7;
        cp16(sb + row * FPB + c * 16, base + (size_t)(qt * 128 + row) * QKVN + c * 8);
    }
    CP_COMMIT();
    #pragma unroll
    for (int p = 0; p < 3; p++) {
        if (p < nkt) {
            fl_load_kv_nb(sb, base, p, p, tid);
            cp_mbar_arrive(mb + p * 8);
        }
    }

    asm volatile("cp.async.wait_group 0;" ::: "memory");
    __syncthreads();

    const int g2 = lid >> 3, li = lid & 7;
    const int a_row = (g2 & 1) * 8 + li, a_kb = (g2 >> 1) * 16;
    const uint32_t qa = sb + (wid * 16 + a_row) * FPB + a_kb;
    uint32_t qh[4][4];
    #pragma unroll
    for (int kc = 0; kc < 4; kc++)
        ldsm4(qh[kc][0], qh[kc][1], qh[kc][2], qh[kc][3], qa + kc * 32);

    float o[8][4];
    #pragma unroll
    for (int nt = 0; nt < 8; nt++)
        #pragma unroll
        for (int e = 0; e < 4; e++) o[nt][e] = 0.f;
    float m0 = -1e30f, m1 = -1e30f, l0 = 0.f, l1 = 0.f;

    const int gq = lid >> 2, t4 = lid & 3;
    const int row0g = qt * 128 + wid * 16 + gq;
    const int row1g = row0g + 8;

    const uint32_t kb_off = (uint32_t)(((g2 >> 1) * 8 + li) * FPB + (g2 & 1) * 16);
    const uint32_t v_off  = (uint32_t)(((g2 & 1) * 8 + li) * FPB + (g2 >> 1) * 16);

    for (int kt = 0; kt < nkt; kt++) {
        const int s = kt % 3;
        mbar_wait(mb + s * 8, (uint32_t)((kt / 3) & 1));
        const uint32_t buf = sb + FL_KV + s * FL_BUF;

        float sc[8][4];
        #pragma unroll
        for (int nt = 0; nt < 8; nt++)
            #pragma unroll
            for (int e = 0; e < 4; e++) sc[nt][e] = 0.f;

        #pragma unroll
        for (int kc = 0; kc < 4; kc++) {
            #pragma unroll
            for (int ntp = 0; ntp < 4; ntp++) {
                uint32_t ka = buf + kb_off + ntp * 16 * FPB + kc * 32;
                uint32_t h0, h1, h2, h3;
                ldsm4(h0, h1, h2, h3, ka);
                mma2(sc[2 * ntp],     qh[kc], h0, h1);
                mma2(sc[2 * ntp + 1], qh[kc], h2, h3);
            }
        }

        if (kt >= 2 * qt) {
            int colb = kt * 64 + 2 * t4;
            #pragma unroll
            for (int nt = 0; nt < 8; nt++) {
                int c0 = colb + nt * 8, c1 = c0 + 1;
                if (c0 > row0g) sc[nt][0] = -1e30f;
                if (c1 > row0g) sc[nt][1] = -1e30f;
                if (c0 > row1g) sc[nt][2] = -1e30f;
                if (c1 > row1g) sc[nt][3] = -1e30f;
            }
        }

        float tm0 = -1e30f, tm1 = -1e30f;
        #pragma unroll
        for (int nt = 0; nt < 8; nt++) {
            tm0 = fmaxf(tm0, fmaxf(sc[nt][0], sc[nt][1]));
            tm1 = fmaxf(tm1, fmaxf(sc[nt][2], sc[nt][3]));
        }
        tm0 = fmaxf(tm0, __shfl_xor_sync(0xffffffffu, tm0, 1));
        tm0 = fmaxf(tm0, __shfl_xor_sync(0xffffffffu, tm0, 2));
        tm1 = fmaxf(tm1, __shfl_xor_sync(0xffffffffu, tm1, 1));
        tm1 = fmaxf(tm1, __shfl_xor_sync(0xffffffffu, tm1, 2));
        float mn0 = fmaxf(m0, tm0), mn1 = fmaxf(m1, tm1);
        float al0 = exp2f(m0 - mn0), al1 = exp2f(m1 - mn1);
        m0 = mn0; m1 = mn1;

        float rs0 = 0.f, rs1 = 0.f;
        #pragma unroll
        for (int nt = 0; nt < 8; nt++) {
            sc[nt][0] = exp2f(sc[nt][0] - mn0); rs0 += sc[nt][0];
            sc[nt][1] = exp2f(sc[nt][1] - mn0); rs0 += sc[nt][1];
            sc[nt][2] = exp2f(sc[nt][2] - mn1); rs1 += sc[nt][2];
            sc[nt][3] = exp2f(sc[nt][3] - mn1); rs1 += sc[nt][3];
        }
        rs0 += __shfl_xor_sync(0xffffffffu, rs0, 1);
        rs0 += __shfl_xor_sync(0xffffffffu, rs0, 2);
        rs1 += __shfl_xor_sync(0xffffffffu, rs1, 1);
        rs1 += __shfl_xor_sync(0xffffffffu, rs1, 2);
        l0 = l0 * al0 + rs0;
        l1 = l1 * al1 + rs1;
        #pragma unroll
        for (int nt = 0; nt < 8; nt++) {
            o[nt][0] *= al0; o[nt][1] *= al0;
            o[nt][2] *= al1; o[nt][3] *= al1;
        }

        uint32_t pa[4][4];
        #pragma unroll
        for (int kc = 0; kc < 4; kc++) {
            pa[kc][0] = f2h2(sc[2 * kc][0],     sc[2 * kc][1]);
            pa[kc][1] = f2h2(sc[2 * kc][2],     sc[2 * kc][3]);
            pa[kc][2] = f2h2(sc[2 * kc + 1][0], sc[2 * kc + 1][1]);
            pa[kc][3] = f2h2(sc[2 * kc + 1][2], sc[2 * kc + 1][3]);
        }

        #pragma unroll
        for (int kc = 0; kc < 4; kc++) {
            #pragma unroll
            for (int ntp = 0; ntp < 4; ntp++) {
                uint32_t va = buf + FL_TILE + kc * 16 * FPB + ntp * 32 + v_off;
                uint32_t h0, h1, h2, h3;
                ldsm4t(h0, h1, h2, h3, va);
                mma2(o[2 * ntp],     pa[kc], h0, h1);
                mma2(o[2 * ntp + 1], pa[kc], h2, h3);
            }
        }

        if (lid == 0) mbar_arrive(mb + 24 + s * 8);

        if (kt + 3 < nkt) {
            mbar_wait(mb + 24 + s * 8, (uint32_t)((kt / 3) & 1));
            fl_load_kv_nb(sb, base, kt + 3, s, tid);
            cp_mbar_arrive(mb + s * 8);
        }
    }

    float iv0 = 1.f / l0, iv1 = 1.f / l1;
    size_t r0 = (size_t)b * SS + qt * 128 + wid * 16 + gq;
    size_t r1 = r0 + 8;
    #pragma unroll
    for (int nt = 0; nt < 8; nt++) {
        int col = h * 64 + nt * 8 + 2 * t4;
        *(__half2*)(z + r0 * DD + col) = __floats2half2_rn(o[nt][0] * iv0, o[nt][1] * iv0);
        *(__half2*)(z + r1 * DD + col) = __floats2half2_rn(o[nt][2] * iv1, o[nt][3] * iv1);
    }
}

// ---------------------------------------------------------------------------
// Launch
// ---------------------------------------------------------------------------
extern "C" void kernel_launch(void* const* d_in, const int* in_sizes, int n_in,
                              void* d_out, int out_size) {
    (void)in_sizes; (void)n_in; (void)out_size;
    const float* resid_pre = (const float*)d_in[0];
    const float* ln1_w = (const float*)d_in[1];
    const float* ln1_b = (const float*)d_in[2];
    const float* W_Q   = (const float*)d_in[3];
    const float* W_K   = (const float*)d_in[4];
    const float* W_V   = (const float*)d_in[5];
    const float* W_O   = (const float*)d_in[6];
    const float* b_Q   = (const float*)d_in[7];
    const float* b_K   = (const float*)d_in[8];
    const float* b_V   = (const float*)d_in[9];
    const float* b_O   = (const float*)d_in[10];
    const float* ln2_w = (const float*)d_in[11];
    const float* ln2_b = (const float*)d_in[12];
    const float* W_in  = (const float*)d_in[13];
    const float* b_in  = (const float*)d_in[14];
    const float* W_out = (const float*)d_in[15];
    const float* b_out = (const float*)d_in[16];
    float* out = (float*)d_out;

    __half *p_x1, *p_wqkv, *p_qkv, *p_z, *p_wo, *p_x2, *p_win, *p_h, *p_wout;
    float *p_bqkv, *p_rmid;
    cudaGetSymbolAddress((void**)&p_x1, g_x1);
    cudaGetSymbolAddress((void**)&p_wqkv, g_wqkv);
    cudaGetSymbolAddress((void**)&p_bqkv, g_bqkv);
    cudaGetSymbolAddress((void**)&p_qkv, g_qkv);
    cudaGetSymbolAddress((void**)&p_z, g_z);
    cudaGetSymbolAddress((void**)&p_wo, g_wo);
    cudaGetSymbolAddress((void**)&p_rmid, g_rmid);
    cudaGetSymbolAddress((void**)&p_x2, g_x2);
    cudaGetSymbolAddress((void**)&p_win, g_win);
    cudaGetSymbolAddress((void**)&p_h, g_h);
    cudaGetSymbolAddress((void**)&p_wout, g_wout);

    cudaFuncSetAttribute(flash2, cudaFuncAttributeMaxDynamicSharedMemorySize, FLASH2_SMEM);
    cudaFuncSetAttribute(gemm_hmma<1>, cudaFuncAttributeMaxDynamicSharedMemorySize, GEMM_SMEM);
    cudaFuncSetAttribute(gemm_hmma<2>, cudaFuncAttributeMaxDynamicSharedMemorySize, GEMM_SMEM);
    cudaFuncSetAttribute(gemm_hmma<3>, cudaFuncAttributeMaxDynamicSharedMemorySize, GEMM_SMEM);

    // ALL prep (weight conversions + bias pack + LN1) in one launch
    prep_kernel<<<PREP_BLOCKS, 256>>>(W_Q, W_K, W_V, b_Q, b_K, b_V,
                                      W_O, W_in, W_out,
                                      resid_pre, ln1_w, ln1_b);

    // QKV projection -> fp16 (Q scaled by 0.125*log2e)
    gemm_hmma<3><<<dim3(QKVN / 128, BSS / 128), 256, GEMM_SMEM>>>(
        p_x1, p_wqkv, p_bqkv, nullptr, nullptr, p_qkv, BSS, QKVN, DD);

    // flash attention (tensor cores, base-2 softmax, de-phased ring) -> z
    flash2<<<dim3(SS / 128, HH, BB), 256, FLASH2_SMEM>>>(p_qkv, p_z);

    // O projection + residual -> rmid fp32
    gemm_hmma<2><<<dim3(DD / 128, BSS / 128), 256, GEMM_SMEM>>>(
        p_z, p_wo, b_O, resid_pre, p_rmid, nullptr, BSS, DD, DD);

    // LN2
    ln_kernel<<<BSS, 256>>>(p_rmid, ln2_w, ln2_b, p_x2);

    // MLP in + gelu -> h fp16
    gemm_hmma<1><<<dim3(DMM / 128, BSS / 128), 256, GEMM_SMEM>>>(
        p_x2, p_win, b_in, nullptr, nullptr, p_h, BSS, DMM, DD);

    // MLP out + residual -> out fp32
    gemm_hmma<2><<<dim3(DD / 128, BSS / 128), 256, GEMM_SMEM>>>(
        p_h, p_wout, b_out, p_rmid, out, nullptr, BSS, DD, DMM);
}